// round 3
// baseline (speedup 1.0000x reference)
#include <cuda_runtime.h>
#include <cuda_bf16.h>
#include <cstdint>

// ---------------- constants ----------------
#define BATCH 16
#define N1 8192
#define S1 512
#define S2 128
#define NS 64   // nsample

// ---------------- device scratch ----------------
__device__ float g_xyz1[BATCH * S1 * 3];
__device__ float g_xyz2[BATCH * S2 * 3];
__device__ int   g_idx1[BATCH * S1 * NS];
__device__ int   g_idx2[BATCH * S2 * NS];
__device__ float g_feat1[BATCH * S1 * 128];
__device__ float g_feat2[BATCH * S2 * 256];
__device__ float g_A3[BATCH * S2 * 259];
__device__ float g_H1[BATCH * S2 * 512];
__device__ float g_H2[BATCH * S2 * 1024];

static __device__ __forceinline__ unsigned long long umax64(unsigned long long a, unsigned long long b) {
    return a > b ? a : b;
}

// ---------------- FPS ----------------
// One block per batch. Points live in registers. Emits new_xyz directly.
// Matches reference: emit `last` (starting at 0) then update mind w/ dists to `last`,
// argmax (first-index tiebreak) -> next.
template<int N, int TPB>
__global__ void __launch_bounds__(TPB) fps_kernel(const float* __restrict__ pts,
                                                  float* __restrict__ outxyz, int NP) {
    constexpr int PPT = N / TPB;
    constexpr int NW  = TPB / 32;
    int b = blockIdx.x, tid = threadIdx.x;
    const float* P = pts + (size_t)b * N * 3;

    float px[PPT], py[PPT], pz[PPT], mind[PPT];
#pragma unroll
    for (int j = 0; j < PPT; j++) {
        int i = j * TPB + tid;
        px[j] = P[i * 3 + 0];
        py[j] = P[i * 3 + 1];
        pz[j] = P[i * 3 + 2];
        mind[j] = 1e10f;
    }

    __shared__ unsigned long long s_red[NW];
    __shared__ float s_pt[3];

    int last = 0;
    for (int it = 0; it < NP; it++) {
        if (tid == (last & (TPB - 1))) {
            int j = last / TPB;
            s_pt[0] = px[j]; s_pt[1] = py[j]; s_pt[2] = pz[j];
            float* o = outxyz + ((size_t)b * NP + it) * 3;
            o[0] = px[j]; o[1] = py[j]; o[2] = pz[j];
        }
        __syncthreads();
        float lx = s_pt[0], ly = s_pt[1], lz = s_pt[2];

        unsigned long long best = 0ull;
#pragma unroll
        for (int j = 0; j < PPT; j++) {
            float dx = __fsub_rn(px[j], lx);
            float dy = __fsub_rn(py[j], ly);
            float dz = __fsub_rn(pz[j], lz);
            float d = __fadd_rn(__fadd_rn(__fmul_rn(dx, dx), __fmul_rn(dy, dy)), __fmul_rn(dz, dz));
            float m = fminf(mind[j], d);
            mind[j] = m;
            int i = j * TPB + tid;
            unsigned long long pk =
                ((unsigned long long)__float_as_uint(m) << 32) | (unsigned)(N - 1 - i);
            best = umax64(best, pk);
        }
#pragma unroll
        for (int off = 16; off; off >>= 1)
            best = umax64(best, __shfl_down_sync(0xffffffffu, best, off));
        if ((tid & 31) == 0) s_red[tid >> 5] = best;
        __syncthreads();
        unsigned long long r = s_red[0];
#pragma unroll
        for (int w = 1; w < NW; w++) r = umax64(r, s_red[w]);
        last = N - 1 - (int)(r & 0xffffffffu);
    }
}

// ---------------- ball query ----------------
// Warp per center; ordered first-NS hits, pad with first hit, N-1 if none.
// Expanded distance form matching the reference exactly (no FMA contraction).
__global__ void ball_query_kernel(const float* __restrict__ pts,
                                  const float* __restrict__ centers,
                                  int* __restrict__ outidx,
                                  int N, int S, int total, float r2) {
    int gw = (blockIdx.x * blockDim.x + threadIdx.x) >> 5;
    int lane = threadIdx.x & 31;
    if (gw >= total) return;
    int b = gw / S;
    const float* C = centers + (size_t)gw * 3;
    float cx = C[0], cy = C[1], cz = C[2];
    float cn = __fadd_rn(__fadd_rn(__fmul_rn(cx, cx), __fmul_rn(cy, cy)), __fmul_rn(cz, cz));
    const float* P = pts + (size_t)b * N * 3;
    int* out = outidx + (size_t)gw * NS;

    int cnt = 0, firstIdx = -1;
    for (int base = 0; base < N; base += 32) {
        int i = base + lane;
        float qx = P[i * 3 + 0], qy = P[i * 3 + 1], qz = P[i * 3 + 2];
        float pn = __fadd_rn(__fadd_rn(__fmul_rn(qx, qx), __fmul_rn(qy, qy)), __fmul_rn(qz, qz));
        float dt = __fadd_rn(__fadd_rn(__fmul_rn(cx, qx), __fmul_rn(cy, qy)), __fmul_rn(cz, qz));
        float d2 = __fsub_rn(__fadd_rn(cn, pn), __fmul_rn(2.0f, dt));
        unsigned m = __ballot_sync(0xffffffffu, d2 < r2);
        if (lane == 0) {
            while (m && cnt < NS) {
                int p = __ffs(m) - 1;
                m &= m - 1;
                if (firstIdx < 0) firstIdx = base + p;
                out[cnt++] = base + p;
            }
        }
        cnt = __shfl_sync(0xffffffffu, cnt, 0);
        if (cnt >= NS) break;
    }
    if (lane == 0) {
        int fill = (cnt == 0) ? (N - 1) : firstIdx;
        for (int j = cnt; j < NS; j++) out[j] = fill;
    }
}

// ---------------- SA1 fused group + MLP(3->64->128) + maxpool ----------------
// Block per (b,s), 128 threads.
__global__ void __launch_bounds__(128) sa1_kernel(const float* __restrict__ x,
                                                  const float* __restrict__ cxyz,
                                                  const int* __restrict__ idx,
                                                  const float* __restrict__ W1a,
                                                  const float* __restrict__ b1a,
                                                  const float* __restrict__ W1b,
                                                  const float* __restrict__ b1b,
                                                  float* __restrict__ feat) {
    int gblk = blockIdx.x;          // b*512 + s
    int b = gblk >> 9;
    int t = threadIdx.x;

    __shared__ float s_g[NS][4];     // grouped xyz (padded)
    __shared__ float s_h1[NS][64];   // hidden layer 1
    __shared__ float s_w[64][3];
    __shared__ float s_b[64];

    float cx = cxyz[gblk * 3 + 0], cy = cxyz[gblk * 3 + 1], cz = cxyz[gblk * 3 + 2];
    if (t < NS) {
        int i = idx[(size_t)gblk * NS + t];
        const float* p = x + ((size_t)b * N1 + i) * 3;
        s_g[t][0] = p[0] - cx;
        s_g[t][1] = p[1] - cy;
        s_g[t][2] = p[2] - cz;
        s_b[t] = b1a[t];
    }
    for (int e = t; e < 64 * 3; e += 128) ((float*)s_w)[e] = W1a[e];
    __syncthreads();

    // layer 1: h1[k][o] = relu(g[k] . W1a[o] + b1a[o])
#pragma unroll
    for (int e = t; e < NS * 64; e += 128) {
        int k = e >> 6, o = e & 63;
        float v = s_g[k][0] * s_w[o][0] + s_g[k][1] * s_w[o][1] + s_g[k][2] * s_w[o][2] + s_b[o];
        s_h1[k][o] = fmaxf(v, 0.f);
    }
    __syncthreads();

    // layer 2 + maxpool: thread t -> output channel t
    float w[64];
#pragma unroll
    for (int c = 0; c < 64; c += 4) {
        float4 wv = *reinterpret_cast<const float4*>(&W1b[(size_t)t * 64 + c]);
        w[c] = wv.x; w[c + 1] = wv.y; w[c + 2] = wv.z; w[c + 3] = wv.w;
    }
    float bias = b1b[t];
    float m = 0.f;
#pragma unroll 4
    for (int k = 0; k < NS; k++) {
        float dot = 0.f;
#pragma unroll
        for (int c = 0; c < 64; c += 4) {
            float4 h = *reinterpret_cast<const float4*>(&s_h1[k][c]);
            dot += h.x * w[c] + h.y * w[c + 1] + h.z * w[c + 2] + h.w * w[c + 3];
        }
        m = fmaxf(m, fmaxf(dot + bias, 0.f));
    }
    feat[(size_t)gblk * 128 + t] = m;
}

// ---------------- SA2 fused group + MLP(131->128->256) + maxpool ----------------
// Block per (b,s), 256 threads. Dynamic smem: s_g[64][132] + s_h1[64][128].
__global__ void __launch_bounds__(256) sa2_kernel(const float* __restrict__ xyz1,
                                                  const float* __restrict__ cxyz,
                                                  const int* __restrict__ idx,
                                                  const float* __restrict__ feat1,
                                                  const float* __restrict__ W2a,
                                                  const float* __restrict__ b2a,
                                                  const float* __restrict__ W2b,
                                                  const float* __restrict__ b2b,
                                                  float* __restrict__ feat2) {
    extern __shared__ float sm[];
    float* s_g = sm;                 // 64 * 132
    float* s_h1 = sm + 64 * 132;     // 64 * 128

    int gblk = blockIdx.x;           // b*128 + s
    int b = gblk >> 7;
    int t = threadIdx.x;
    float cx = cxyz[gblk * 3 + 0], cy = cxyz[gblk * 3 + 1], cz = cxyz[gblk * 3 + 2];

    // stage A: gather grouped features [64][131] = [xyz-diff(3), feat1(128)]
    // one k-row per half-warp chunk: thread t handles rows, idx loaded once per row
    for (int k = t >> 2; k < NS; k += 64) {
        int i = __ldg(&idx[(size_t)gblk * NS + k]);
        int sub = t & 3;
        // 4 threads cover 131 channels: ch = sub, sub+4, ...
        if (sub < 3) {
            float pv = xyz1[((size_t)b * S1 + i) * 3 + sub];
            s_g[k * 132 + sub] = pv - (sub == 0 ? cx : (sub == 1 ? cy : cz));
        }
        const float* f = feat1 + ((size_t)b * S1 + i) * 128;
        for (int c = sub; c < 128; c += 4)
            s_g[k * 132 + 3 + c] = f[c];
    }
    __syncthreads();

    // stage B: h1[k][o] = relu(g[k] . W2a[o] + b2a[o]); thread -> (o = t&127, k-half = t>>7)
    {
        int o = t & 127, kh = t >> 7;
        float acc[32];
#pragma unroll
        for (int k = 0; k < 32; k++) acc[k] = 0.f;
        const float* wrow = W2a + (size_t)o * 131;
#pragma unroll
        for (int ct = 0; ct < 4; ct++) {
            float w[32];
#pragma unroll
            for (int c = 0; c < 32; c++) w[c] = wrow[ct * 32 + c];
#pragma unroll
            for (int k = 0; k < 32; k++) {
                const float* gr = s_g + (size_t)(kh * 32 + k) * 132 + ct * 32;
                float a = 0.f;
#pragma unroll
                for (int c = 0; c < 32; c += 4) {
                    float4 h = *reinterpret_cast<const float4*>(&gr[c]);
                    a += h.x * w[c] + h.y * w[c + 1] + h.z * w[c + 2] + h.w * w[c + 3];
                }
                acc[k] += a;
            }
        }
        float w0 = wrow[128], w1 = wrow[129], w2 = wrow[130];
        float bias = b2a[o];
#pragma unroll
        for (int k = 0; k < 32; k++) {
            const float* gr = s_g + (size_t)(kh * 32 + k) * 132;
            float v = acc[k] + gr[128] * w0 + gr[129] * w1 + gr[130] * w2 + bias;
            s_h1[(size_t)(kh * 32 + k) * 128 + o] = fmaxf(v, 0.f);
        }
    }
    __syncthreads();

    // stage C: out[o2] = max_k relu(h1[k] . W2b[o2] + b2b[o2]); thread -> o2 = t
    {
        int o = t;
        const float* wrow = W2b + (size_t)o * 128;
        float bias = b2b[o];
        float m = 0.f;
#pragma unroll
        for (int kh = 0; kh < 2; kh++) {
            float acc[32];
#pragma unroll
            for (int k = 0; k < 32; k++) acc[k] = 0.f;
#pragma unroll
            for (int ct = 0; ct < 4; ct++) {
                float w[32];
#pragma unroll
                for (int c = 0; c < 32; c += 4) {
                    float4 wv = *reinterpret_cast<const float4*>(&wrow[ct * 32 + c]);
                    w[c] = wv.x; w[c + 1] = wv.y; w[c + 2] = wv.z; w[c + 3] = wv.w;
                }
#pragma unroll
                for (int k = 0; k < 32; k++) {
                    const float* hr = s_h1 + (size_t)(kh * 32 + k) * 128 + ct * 32;
                    float a = 0.f;
#pragma unroll
                    for (int c = 0; c < 32; c += 4) {
                        float4 h = *reinterpret_cast<const float4*>(&hr[c]);
                        a += h.x * w[c] + h.y * w[c + 1] + h.z * w[c + 2] + h.w * w[c + 3];
                    }
                    acc[k] += a;
                }
            }
#pragma unroll
            for (int k = 0; k < 32; k++)
                m = fmaxf(m, fmaxf(acc[k] + bias, 0.f));
        }
        feat2[(size_t)gblk * 256 + o] = m;
    }
}

// ---------------- concat xyz2 + feat2 -> A3 [2048][259] ----------------
__global__ void concat_kernel(const float* __restrict__ xyz2,
                              const float* __restrict__ feat2,
                              float* __restrict__ A3) {
    int e = blockIdx.x * blockDim.x + threadIdx.x;
    if (e >= BATCH * S2 * 259) return;
    int r = e / 259, c = e - r * 259;
    A3[e] = (c < 3) ? xyz2[r * 3 + c] : feat2[(size_t)r * 256 + (c - 3)];
}

// ---------------- tiled GEMM: C = relu(A[M,K] * W[N,K]^T + bias) ----------------
// 64x64 tile, BK=16, 256 threads, 4x4 microtile.
__global__ void __launch_bounds__(256) gemm_relu_kernel(const float* __restrict__ A, int lda,
                                                        const float* __restrict__ W, int ldw,
                                                        const float* __restrict__ bias,
                                                        float* __restrict__ C, int ldc, int K) {
    __shared__ float As[16][68];
    __shared__ float Ws[16][68];
    int bm = blockIdx.y * 64, bn = blockIdx.x * 64;
    int t = threadIdx.x;
    int tx = t & 15, ty = t >> 4;

    float acc[4][4];
#pragma unroll
    for (int i = 0; i < 4; i++)
#pragma unroll
        for (int j = 0; j < 4; j++) acc[i][j] = 0.f;

    for (int k0 = 0; k0 < K; k0 += 16) {
#pragma unroll
        for (int l = 0; l < 4; l++) {
            int e = t + l * 256;
            int m = e >> 4, kk = e & 15;
            int gk = k0 + kk;
            As[kk][m] = (gk < K) ? A[(size_t)(bm + m) * lda + gk] : 0.f;
        }
#pragma unroll
        for (int l = 0; l < 4; l++) {
            int e = t + l * 256;
            int n = e >> 4, kk = e & 15;
            int gk = k0 + kk;
            Ws[kk][n] = (gk < K) ? W[(size_t)(bn + n) * ldw + gk] : 0.f;
        }
        __syncthreads();
#pragma unroll
        for (int kk = 0; kk < 16; kk++) {
            float4 av = *reinterpret_cast<const float4*>(&As[kk][ty * 4]);
            float4 wv = *reinterpret_cast<const float4*>(&Ws[kk][tx * 4]);
            float a0 = av.x, a1 = av.y, a2 = av.z, a3 = av.w;
            float w0 = wv.x, w1 = wv.y, w2 = wv.z, w3 = wv.w;
            acc[0][0] += a0 * w0; acc[0][1] += a0 * w1; acc[0][2] += a0 * w2; acc[0][3] += a0 * w3;
            acc[1][0] += a1 * w0; acc[1][1] += a1 * w1; acc[1][2] += a1 * w2; acc[1][3] += a1 * w3;
            acc[2][0] += a2 * w0; acc[2][1] += a2 * w1; acc[2][2] += a2 * w2; acc[2][3] += a2 * w3;
            acc[3][0] += a3 * w0; acc[3][1] += a3 * w1; acc[3][2] += a3 * w2; acc[3][3] += a3 * w3;
        }
        __syncthreads();
    }
#pragma unroll
    for (int i = 0; i < 4; i++) {
        int row = bm + ty * 4 + i;
#pragma unroll
        for (int j = 0; j < 4; j++) {
            int col = bn + tx * 4 + j;
            C[(size_t)row * ldc + col] = fmaxf(acc[i][j] + bias[col], 0.f);
        }
    }
}

// ---------------- final max over 128 rows per batch ----------------
__global__ void max_kernel(const float* __restrict__ H, float* __restrict__ out) {
    int e = blockIdx.x * blockDim.x + threadIdx.x; // 16 * 1024
    int b = e >> 10, o = e & 1023;
    const float* p = H + (size_t)b * S2 * 1024 + o;
    float m = p[0];
#pragma unroll 8
    for (int k = 1; k < S2; k++) m = fmaxf(m, p[(size_t)k * 1024]);
    out[e] = m;
}

// ---------------- launch ----------------
extern "C" void kernel_launch(void* const* d_in, const int* in_sizes, int n_in,
                              void* d_out, int out_size) {
    const float* x   = (const float*)d_in[0];
    const float* W1a = (const float*)d_in[1];
    const float* b1a = (const float*)d_in[2];
    const float* W1b = (const float*)d_in[3];
    const float* b1b = (const float*)d_in[4];
    const float* W2a = (const float*)d_in[5];
    const float* b2a = (const float*)d_in[6];
    const float* W2b = (const float*)d_in[7];
    const float* b2b = (const float*)d_in[8];
    const float* W3a = (const float*)d_in[9];
    const float* b3a = (const float*)d_in[10];
    const float* W3b = (const float*)d_in[11];
    const float* b3b = (const float*)d_in[12];
    float* out = (float*)d_out;

    float *xyz1, *xyz2, *feat1, *feat2, *A3, *H1, *H2;
    int *idx1, *idx2;
    cudaGetSymbolAddress((void**)&xyz1, g_xyz1);
    cudaGetSymbolAddress((void**)&xyz2, g_xyz2);
    cudaGetSymbolAddress((void**)&idx1, g_idx1);
    cudaGetSymbolAddress((void**)&idx2, g_idx2);
    cudaGetSymbolAddress((void**)&feat1, g_feat1);
    cudaGetSymbolAddress((void**)&feat2, g_feat2);
    cudaGetSymbolAddress((void**)&A3, g_A3);
    cudaGetSymbolAddress((void**)&H1, g_H1);
    cudaGetSymbolAddress((void**)&H2, g_H2);

    // radii squared, computed as in the reference (double product, cast to f32)
    const float r2_1 = (float)(0.2 * 0.2);
    const float r2_2 = (float)(0.4 * 0.4);

    // SA1
    fps_kernel<N1, 1024><<<BATCH, 1024>>>(x, xyz1, S1);
    ball_query_kernel<<<(BATCH * S1) / 8, 256>>>(x, xyz1, idx1, N1, S1, BATCH * S1, r2_1);
    sa1_kernel<<<BATCH * S1, 128>>>(x, xyz1, idx1, W1a, b1a, W1b, b1b, feat1);

    // SA2
    fps_kernel<S1, 512><<<BATCH, 512>>>(xyz1, xyz2, S2);
    ball_query_kernel<<<(BATCH * S2) / 8, 256>>>(xyz1, xyz2, idx2, S1, S2, BATCH * S2, r2_2);
    size_t sa2_smem = (64 * 132 + 64 * 128) * sizeof(float);
    cudaFuncSetAttribute(sa2_kernel, cudaFuncAttributeMaxDynamicSharedMemorySize, (int)sa2_smem);
    sa2_kernel<<<BATCH * S2, 256, sa2_smem>>>(xyz1, xyz2, idx2, feat1,
                                              W2a, b2a, W2b, b2b, feat2);

    // Head
    concat_kernel<<<(BATCH * S2 * 259 + 255) / 256, 256>>>(xyz2, feat2, A3);
    gemm_relu_kernel<<<dim3(512 / 64, (BATCH * S2) / 64), 256>>>(A3, 259, W3a, 259, b3a, H1, 512, 259);
    gemm_relu_kernel<<<dim3(1024 / 64, (BATCH * S2) / 64), 256>>>(H1, 512, W3b, 512, b3b, H2, 1024, 512);
    max_kernel<<<(BATCH * 1024) / 256, 256>>>(H2, out);
}

// round 7
// speedup vs baseline: 1.8122x; 1.8122x over previous
#include <cuda_runtime.h>
#include <cuda_bf16.h>
#include <cstdint>

#define BATCH 16
#define N1 8192
#define S1 512
#define S2 128
#define NS 64

typedef unsigned long long u64;

// ---------------- device scratch ----------------
__device__ float g_xyz1[BATCH * S1 * 3];
__device__ float g_xyz2[BATCH * S2 * 3];
__device__ int   g_idx1[BATCH * S1 * NS];
__device__ int   g_idx2[BATCH * S2 * NS];
__device__ float g_feat1[BATCH * S1 * 128];
__device__ float g_feat2[BATCH * S2 * 256];
__device__ float g_A3[BATCH * S2 * 259];
__device__ float g_H1[BATCH * S2 * 512];
__device__ float g_H2[BATCH * S2 * 1024];

static __device__ __forceinline__ u64 umax64(u64 a, u64 b) { return a > b ? a : b; }

// packed f32x2 helpers (bit-exact: two independent fp32 FMAs)
static __device__ __forceinline__ u64 pk2(float x, float y) {
    u64 r; asm("mov.b64 %0, {%1, %2};" : "=l"(r) : "f"(x), "f"(y)); return r;
}
static __device__ __forceinline__ float2 upk2(u64 v) {
    float2 f; asm("mov.b64 {%0, %1}, %2;" : "=f"(f.x), "=f"(f.y) : "l"(v)); return f;
}
static __device__ __forceinline__ void ffma2(u64& d, u64 a, u64 b) {
    asm("fma.rn.f32x2 %0, %1, %2, %0;" : "+l"(d) : "l"(a), "l"(b));
}

// ---------------- FPS: one barrier per iteration ----------------
template<int N, int TPB>
__global__ void __launch_bounds__(TPB) fps_kernel(const float* __restrict__ pts,
                                                  float* __restrict__ outxyz, int NP) {
    constexpr int PPT = N / TPB;
    constexpr int NW  = TPB / 32;
    extern __shared__ float sh[];
    float* s_pts = sh;                                   // N*3
    u64* s_red = (u64*)(sh + N * 3);                     // 2*NW

    int b = blockIdx.x, tid = threadIdx.x;
    int wid = tid >> 5, lane = tid & 31;
    const float* P = pts + (size_t)b * N * 3;

    float px[PPT], py[PPT], pz[PPT], mind[PPT];
#pragma unroll
    for (int j = 0; j < PPT; j++) {
        int i = j * TPB + tid;
        px[j] = P[i * 3 + 0]; py[j] = P[i * 3 + 1]; pz[j] = P[i * 3 + 2];
        s_pts[i * 3 + 0] = px[j]; s_pts[i * 3 + 1] = py[j]; s_pts[i * 3 + 2] = pz[j];
        mind[j] = 1e10f;
    }
    __syncthreads();

    int last = 0;
    for (int it = 0; it < NP; it++) {
        if (tid == 0) {
            float* o = outxyz + ((size_t)b * NP + it) * 3;
            o[0] = s_pts[last * 3 + 0]; o[1] = s_pts[last * 3 + 1]; o[2] = s_pts[last * 3 + 2];
        }
        float lx = s_pts[last * 3 + 0], ly = s_pts[last * 3 + 1], lz = s_pts[last * 3 + 2];

        u64 best = 0ull;
#pragma unroll
        for (int j = 0; j < PPT; j++) {
            float dx = __fsub_rn(px[j], lx);
            float dy = __fsub_rn(py[j], ly);
            float dz = __fsub_rn(pz[j], lz);
            float d = __fadd_rn(__fadd_rn(__fmul_rn(dx, dx), __fmul_rn(dy, dy)), __fmul_rn(dz, dz));
            float m = fminf(mind[j], d);
            mind[j] = m;
            int i = j * TPB + tid;
            u64 pk = ((u64)__float_as_uint(m) << 32) | (unsigned)(N - 1 - i);
            best = umax64(best, pk);
        }
#pragma unroll
        for (int off = 16; off; off >>= 1)
            best = umax64(best, __shfl_down_sync(0xffffffffu, best, off));
        if (lane == 0) s_red[(it & 1) * NW + wid] = best;
        __syncthreads();
        const u64* rr = s_red + (it & 1) * NW;
        u64 a0 = rr[0], a1 = rr[1], a2 = rr[2], a3 = rr[3];
#pragma unroll
        for (int w = 4; w < NW; w += 4) {
            a0 = umax64(a0, rr[w]); a1 = umax64(a1, rr[w + 1]);
            a2 = umax64(a2, rr[w + 2]); a3 = umax64(a3, rr[w + 3]);
        }
        last = N - 1 - (int)(umax64(umax64(a0, a1), umax64(a2, a3)) & 0xffffffffu);
    }
}

// ---------------- ball query ----------------
__global__ void ball_query_kernel(const float* __restrict__ pts,
                                  const float* __restrict__ centers,
                                  int* __restrict__ outidx,
                                  int N, int S, int total, float r2) {
    int gw = (blockIdx.x * blockDim.x + threadIdx.x) >> 5;
    int lane = threadIdx.x & 31;
    if (gw >= total) return;
    int b = gw / S;
    const float* C = centers + (size_t)gw * 3;
    float cx = C[0], cy = C[1], cz = C[2];
    float cn = __fadd_rn(__fadd_rn(__fmul_rn(cx, cx), __fmul_rn(cy, cy)), __fmul_rn(cz, cz));
    const float* P = pts + (size_t)b * N * 3;
    int* out = outidx + (size_t)gw * NS;

    int cnt = 0, firstIdx = -1;
    for (int base = 0; base < N; base += 32) {
        int i = base + lane;
        float qx = P[i * 3 + 0], qy = P[i * 3 + 1], qz = P[i * 3 + 2];
        float pn = __fadd_rn(__fadd_rn(__fmul_rn(qx, qx), __fmul_rn(qy, qy)), __fmul_rn(qz, qz));
        float dt = __fadd_rn(__fadd_rn(__fmul_rn(cx, qx), __fmul_rn(cy, qy)), __fmul_rn(cz, qz));
        float d2 = __fsub_rn(__fadd_rn(cn, pn), __fmul_rn(2.0f, dt));
        unsigned m = __ballot_sync(0xffffffffu, d2 < r2);
        if (lane == 0) {
            while (m && cnt < NS) {
                int p = __ffs(m) - 1;
                m &= m - 1;
                if (firstIdx < 0) firstIdx = base + p;
                out[cnt++] = base + p;
            }
        }
        cnt = __shfl_sync(0xffffffffu, cnt, 0);
        if (cnt >= NS) break;
    }
    if (lane == 0) {
        int fill = (cnt == 0) ? (N - 1) : firstIdx;
        for (int j = cnt; j < NS; j++) out[j] = fill;
    }
}

// ---------------- SA1: group + MLP(3->64->128) + maxpool, FFMA2-tiled ----------------
__global__ void __launch_bounds__(128) sa1_kernel(const float* __restrict__ x,
                                                  const float* __restrict__ cxyz,
                                                  const int* __restrict__ idx,
                                                  const float* __restrict__ W1a,
                                                  const float* __restrict__ b1a,
                                                  const float* __restrict__ W1b,
                                                  const float* __restrict__ b1b,
                                                  float* __restrict__ feat) {
    extern __shared__ float s1[];
    float* s_hT   = s1;                  // [c=64][k pad 68]
    float* s_wT   = s_hT + 64 * 68;      // [c=64][o pad 132]
    float* s_m    = s_wT + 64 * 132;     // [8][128] (also W1a staging: 192 floats)
    float* s_g    = s_m + 8 * 128;       // [64][4]
    float* s_bias = s_g + 64 * 4;        // [64]

    int gblk = blockIdx.x;
    int b = gblk >> 9;
    int t = threadIdx.x;

    float cx = cxyz[gblk * 3 + 0], cy = cxyz[gblk * 3 + 1], cz = cxyz[gblk * 3 + 2];
    if (t < 64) {
        int i = idx[(size_t)gblk * NS + t];
        const float* p = x + ((size_t)b * N1 + i) * 3;
        s_g[t * 4 + 0] = p[0] - cx;
        s_g[t * 4 + 1] = p[1] - cy;
        s_g[t * 4 + 2] = p[2] - cz;
        s_bias[t] = b1a[t];
    }
    // W1a staging: FULL 192 elements (fixed: previous version skipped [64,128))
    for (int e = t; e < 64 * 3; e += 128) s_m[e] = W1a[e];
    for (int e = t; e < 128 * 64; e += 128) {                       // W1b^T
        int o = e >> 6, c = e & 63;
        s_wT[c * 132 + o] = W1b[e];
    }
    __syncthreads();

    // layer1 -> s_hT[c][k]
    for (int e = t; e < 64 * 64; e += 128) {
        int k = e >> 6, o1 = e & 63;
        float v = s_g[k * 4 + 0] * s_m[o1 * 3 + 0] + s_g[k * 4 + 1] * s_m[o1 * 3 + 1]
                + s_g[k * 4 + 2] * s_m[o1 * 3 + 2] + s_bias[o1];
        s_hT[o1 * 68 + k] = fmaxf(v, 0.f);
    }
    __syncthreads();

    // layer2: C[k=64][o=128], 8k x 8o per thread, k paired for FFMA2
    int kr = t & 7, oc = t >> 3;   // oc 0..15
    u64 acc[4][8];
#pragma unroll
    for (int i = 0; i < 4; i++)
#pragma unroll
        for (int j = 0; j < 8; j++) acc[i][j] = 0ull;

    for (int c = 0; c < 64; c++) {
        const float* hr = s_hT + c * 68;
        float4 ha = *(const float4*)(hr + kr * 4);
        float4 hb = *(const float4*)(hr + 32 + kr * 4);
        u64 hp[4] = { pk2(ha.x, ha.y), pk2(ha.z, ha.w), pk2(hb.x, hb.y), pk2(hb.z, hb.w) };
        const float* wr = s_wT + c * 132;
        float4 wa = *(const float4*)(wr + oc * 4);
        float4 wb = *(const float4*)(wr + 64 + oc * 4);
        float wv[8] = { wa.x, wa.y, wa.z, wa.w, wb.x, wb.y, wb.z, wb.w };
#pragma unroll
        for (int oo = 0; oo < 8; oo++) {
            u64 wd = pk2(wv[oo], wv[oo]);
#pragma unroll
            for (int kp = 0; kp < 4; kp++) ffma2(acc[kp][oo], hp[kp], wd);
        }
    }
#pragma unroll
    for (int oo = 0; oo < 8; oo++) {
        int o = (oo < 4) ? (oc * 4 + oo) : (64 + oc * 4 + (oo - 4));
        float bias = b1b[o];
        float best = 0.f;
#pragma unroll
        for (int kp = 0; kp < 4; kp++) {
            float2 v = upk2(acc[kp][oo]);
            best = fmaxf(best, fmaxf(v.x + bias, 0.f));
            best = fmaxf(best, fmaxf(v.y + bias, 0.f));
        }
        s_m[kr * 128 + o] = best;
    }
    __syncthreads();
    if (t < 128) {
        float r = s_m[t];
#pragma unroll
        for (int w = 1; w < 8; w++) r = fmaxf(r, s_m[w * 128 + t]);
        feat[(size_t)gblk * 128 + t] = r;
    }
}

// ---------------- SA2: group + MLP(131->128->256) + maxpool, FFMA2-tiled ----------------
__global__ void __launch_bounds__(256) sa2_kernel(const float* __restrict__ xyz1,
                                                  const float* __restrict__ cxyz,
                                                  const int* __restrict__ idx,
                                                  const float* __restrict__ feat1,
                                                  const float* __restrict__ W2a,
                                                  const float* __restrict__ b2a,
                                                  const float* __restrict__ W2b,
                                                  const float* __restrict__ b2b,
                                                  float* __restrict__ feat2) {
    extern __shared__ float s2[];
    float* s_h1T = s2;                       // [o=128][k pad 68]
    float* s_gT  = s2 + 128 * 68;            // [c=131][k pad 68]
    float* s_waT = s_gT + 131 * 68;          // [c=131][o pad 132]
    float* s_wbT = s2 + 128 * 68;            // [c=128][o pad 260]  (reuses gT/waT)
    float* s_m   = s_wbT + 128 * 260;        // [8][256]

    int gblk = blockIdx.x;
    int b = gblk >> 7;
    int t = threadIdx.x;
    float cx = cxyz[gblk * 3 + 0], cy = cxyz[gblk * 3 + 1], cz = cxyz[gblk * 3 + 2];

    // stage A: gather -> s_gT[c][k], 4 threads per k
    {
        int k = t >> 2, sub = t & 3;
        int i = idx[(size_t)gblk * NS + k];
        if (sub < 3) {
            float pv = xyz1[((size_t)b * S1 + i) * 3 + sub];
            s_gT[sub * 68 + k] = pv - (sub == 0 ? cx : (sub == 1 ? cy : cz));
        }
        const float* f = feat1 + ((size_t)b * S1 + i) * 128;
        for (int c = sub; c < 128; c += 4)
            s_gT[(3 + c) * 68 + k] = f[c];
    }
    // W2a^T
    for (int e = t; e < 128 * 131; e += 256) {
        int o = e / 131, c = e - o * 131;
        s_waT[c * 132 + o] = W2a[e];
    }
    __syncthreads();

    int kr = t & 7, oc = t >> 3;  // oc 0..31

    // stage B: h1[k=64][o=128], 8k x 4o per thread
    {
        u64 acc[4][4];
#pragma unroll
        for (int i = 0; i < 4; i++)
#pragma unroll
            for (int j = 0; j < 4; j++) acc[i][j] = 0ull;
        for (int c = 0; c < 131; c++) {
            const float* g = s_gT + c * 68;
            float4 ha = *(const float4*)(g + kr * 4);
            float4 hb = *(const float4*)(g + 32 + kr * 4);
            u64 hp[4] = { pk2(ha.x, ha.y), pk2(ha.z, ha.w), pk2(hb.x, hb.y), pk2(hb.z, hb.w) };
            float4 wv = *(const float4*)(s_waT + c * 132 + oc * 4);
            float wvv[4] = { wv.x, wv.y, wv.z, wv.w };
#pragma unroll
            for (int oo = 0; oo < 4; oo++) {
                u64 wd = pk2(wvv[oo], wvv[oo]);
#pragma unroll
                for (int kp = 0; kp < 4; kp++) ffma2(acc[kp][oo], hp[kp], wd);
            }
        }
#pragma unroll
        for (int oo = 0; oo < 4; oo++) {
            int o = oc * 4 + oo;
            float bias = b2a[o];
#pragma unroll
            for (int kp = 0; kp < 4; kp++) {
                int k0 = (kp < 2) ? (kr * 4 + kp * 2) : (32 + kr * 4 + (kp - 2) * 2);
                float2 v = upk2(acc[kp][oo]);
                float2 r = make_float2(fmaxf(v.x + bias, 0.f), fmaxf(v.y + bias, 0.f));
                *(float2*)(s_h1T + o * 68 + k0) = r;
            }
        }
    }
    __syncthreads();

    // load W2b^T (overwrites gT/waT region)
    for (int e = t; e < 256 * 128; e += 256) {
        int o = e >> 7, c = e & 127;
        s_wbT[c * 260 + o] = W2b[e];
    }
    __syncthreads();

    // stage C: out[k=64][o=256], 8k x 8o per thread, max over k
    {
        u64 acc[4][8];
#pragma unroll
        for (int i = 0; i < 4; i++)
#pragma unroll
            for (int j = 0; j < 8; j++) acc[i][j] = 0ull;
        for (int c = 0; c < 128; c++) {
            const float* h = s_h1T + c * 68;
            float4 ha = *(const float4*)(h + kr * 4);
            float4 hb = *(const float4*)(h + 32 + kr * 4);
            u64 hp[4] = { pk2(ha.x, ha.y), pk2(ha.z, ha.w), pk2(hb.x, hb.y), pk2(hb.z, hb.w) };
            const float* w = s_wbT + c * 260;
            float4 wa = *(const float4*)(w + oc * 4);
            float4 wb = *(const float4*)(w + 128 + oc * 4);
            float wv[8] = { wa.x, wa.y, wa.z, wa.w, wb.x, wb.y, wb.z, wb.w };
#pragma unroll
            for (int oo = 0; oo < 8; oo++) {
                u64 wd = pk2(wv[oo], wv[oo]);
#pragma unroll
                for (int kp = 0; kp < 4; kp++) ffma2(acc[kp][oo], hp[kp], wd);
            }
        }
#pragma unroll
        for (int oo = 0; oo < 8; oo++) {
            int o = (oo < 4) ? (oc * 4 + oo) : (128 + oc * 4 + (oo - 4));
            float bias = b2b[o];
            float best = 0.f;
#pragma unroll
            for (int kp = 0; kp < 4; kp++) {
                float2 v = upk2(acc[kp][oo]);
                best = fmaxf(best, fmaxf(v.x + bias, 0.f));
                best = fmaxf(best, fmaxf(v.y + bias, 0.f));
            }
            s_m[kr * 256 + o] = best;
        }
    }
    __syncthreads();
    {
        float r = s_m[t];
#pragma unroll
        for (int w = 1; w < 8; w++) r = fmaxf(r, s_m[w * 256 + t]);
        feat2[(size_t)gblk * 256 + t] = r;
    }
}

// ---------------- concat xyz2 + feat2 -> A3 [2048][259] ----------------
__global__ void concat_kernel(const float* __restrict__ xyz2,
                              const float* __restrict__ feat2,
                              float* __restrict__ A3) {
    int e = blockIdx.x * blockDim.x + threadIdx.x;
    if (e >= BATCH * S2 * 259) return;
    int r = e / 259, c = e - r * 259;
    A3[e] = (c < 3) ? xyz2[r * 3 + c] : feat2[(size_t)r * 256 + (c - 3)];
}

// ---------------- tiled GEMM: C = relu(A[M,K] * W[N,K]^T + bias), FFMA2 ----------------
__global__ void __launch_bounds__(256) gemm_relu_kernel(const float* __restrict__ A, int lda,
                                                        const float* __restrict__ W, int ldw,
                                                        const float* __restrict__ bias,
                                                        float* __restrict__ C, int ldc, int K) {
    __shared__ float As[16][68];
    __shared__ float Ws[16][68];
    int bm = blockIdx.y * 64, bn = blockIdx.x * 64;
    int t = threadIdx.x;
    int tx = t & 15, ty = t >> 4;

    u64 acc[2][4];
#pragma unroll
    for (int i = 0; i < 2; i++)
#pragma unroll
        for (int j = 0; j < 4; j++) acc[i][j] = 0ull;

    for (int k0 = 0; k0 < K; k0 += 16) {
#pragma unroll
        for (int l = 0; l < 4; l++) {
            int e = t + l * 256;
            int m = e >> 4, kk = e & 15;
            int gk = k0 + kk;
            As[kk][m] = (gk < K) ? A[(size_t)(bm + m) * lda + gk] : 0.f;
        }
#pragma unroll
        for (int l = 0; l < 4; l++) {
            int e = t + l * 256;
            int n = e >> 4, kk = e & 15;
            int gk = k0 + kk;
            Ws[kk][n] = (gk < K) ? W[(size_t)(bn + n) * ldw + gk] : 0.f;
        }
        __syncthreads();
#pragma unroll
        for (int kk = 0; kk < 16; kk++) {
            float4 av = *(const float4*)(&As[kk][ty * 4]);
            float4 wv = *(const float4*)(&Ws[kk][tx * 4]);
            u64 ap[2] = { pk2(av.x, av.y), pk2(av.z, av.w) };
            float wvv[4] = { wv.x, wv.y, wv.z, wv.w };
#pragma unroll
            for (int j = 0; j < 4; j++) {
                u64 wd = pk2(wvv[j], wvv[j]);
                ffma2(acc[0][j], ap[0], wd);
                ffma2(acc[1][j], ap[1], wd);
            }
        }
        __syncthreads();
    }
#pragma unroll
    for (int ip = 0; ip < 2; ip++) {
#pragma unroll
        for (int j = 0; j < 4; j++) {
            float2 v = upk2(acc[ip][j]);
            int col = bn + tx * 4 + j;
            float bb = bias[col];
            int row0 = bm + ty * 4 + ip * 2;
            C[(size_t)row0 * ldc + col]       = fmaxf(v.x + bb, 0.f);
            C[(size_t)(row0 + 1) * ldc + col] = fmaxf(v.y + bb, 0.f);
        }
    }
}

// ---------------- final max over 128 rows per batch ----------------
__global__ void max_kernel(const float* __restrict__ H, float* __restrict__ out) {
    int e = blockIdx.x * blockDim.x + threadIdx.x;
    int b = e >> 10, o = e & 1023;
    const float* p = H + (size_t)b * S2 * 1024 + o;
    float m = p[0];
#pragma unroll 8
    for (int k = 1; k < S2; k++) m = fmaxf(m, p[(size_t)k * 1024]);
    out[e] = m;
}

// ---------------- launch ----------------
extern "C" void kernel_launch(void* const* d_in, const int* in_sizes, int n_in,
                              void* d_out, int out_size) {
    const float* x   = (const float*)d_in[0];
    const float* W1a = (const float*)d_in[1];
    const float* b1a = (const float*)d_in[2];
    const float* W1b = (const float*)d_in[3];
    const float* b1b = (const float*)d_in[4];
    const float* W2a = (const float*)d_in[5];
    const float* b2a = (const float*)d_in[6];
    const float* W2b = (const float*)d_in[7];
    const float* b2b = (const float*)d_in[8];
    const float* W3a = (const float*)d_in[9];
    const float* b3a = (const float*)d_in[10];
    const float* W3b = (const float*)d_in[11];
    const float* b3b = (const float*)d_in[12];
    float* out = (float*)d_out;

    float *xyz1, *xyz2, *feat1, *feat2, *A3, *H1, *H2;
    int *idx1, *idx2;
    cudaGetSymbolAddress((void**)&xyz1, g_xyz1);
    cudaGetSymbolAddress((void**)&xyz2, g_xyz2);
    cudaGetSymbolAddress((void**)&idx1, g_idx1);
    cudaGetSymbolAddress((void**)&idx2, g_idx2);
    cudaGetSymbolAddress((void**)&feat1, g_feat1);
    cudaGetSymbolAddress((void**)&feat2, g_feat2);
    cudaGetSymbolAddress((void**)&A3, g_A3);
    cudaGetSymbolAddress((void**)&H1, g_H1);
    cudaGetSymbolAddress((void**)&H2, g_H2);

    const float r2_1 = (float)(0.2 * 0.2);
    const float r2_2 = (float)(0.4 * 0.4);

    // SA1
    size_t fps1_smem = (size_t)N1 * 3 * sizeof(float) + 2 * 16 * sizeof(u64);
    cudaFuncSetAttribute((const void*)fps_kernel<N1, 512>,
                         cudaFuncAttributeMaxDynamicSharedMemorySize, (int)fps1_smem);
    fps_kernel<N1, 512><<<BATCH, 512, fps1_smem>>>(x, xyz1, S1);
    ball_query_kernel<<<(BATCH * S1) / 8, 256>>>(x, xyz1, idx1, N1, S1, BATCH * S1, r2_1);
    size_t sa1_smem = (64 * 68 + 64 * 132 + 8 * 128 + 64 * 4 + 64) * sizeof(float);
    cudaFuncSetAttribute((const void*)sa1_kernel,
                         cudaFuncAttributeMaxDynamicSharedMemorySize, (int)sa1_smem);
    sa1_kernel<<<BATCH * S1, 128, sa1_smem>>>(x, xyz1, idx1, W1a, b1a, W1b, b1b, feat1);

    // SA2
    size_t fps2_smem = (size_t)S1 * 3 * sizeof(float) + 2 * 16 * sizeof(u64);
    fps_kernel<S1, 512><<<BATCH, 512, fps2_smem>>>(xyz1, xyz2, S2);
    ball_query_kernel<<<(BATCH * S2) / 8, 256>>>(xyz1, xyz2, idx2, S1, S2, BATCH * S2, r2_2);
    size_t sa2_smem = (size_t)(128 * 68 + 128 * 260 + 8 * 256) * sizeof(float);
    cudaFuncSetAttribute((const void*)sa2_kernel,
                         cudaFuncAttributeMaxDynamicSharedMemorySize, (int)sa2_smem);
    sa2_kernel<<<BATCH * S2, 256, sa2_smem>>>(xyz1, xyz2, idx2, feat1,
                                              W2a, b2a, W2b, b2b, feat2);

    // Head
    concat_kernel<<<(BATCH * S2 * 259 + 255) / 256, 256>>>(xyz2, feat2, A3);
    gemm_relu_kernel<<<dim3(512 / 64, (BATCH * S2) / 64), 256>>>(A3, 259, W3a, 259, b3a, H1, 512, 259);
    gemm_relu_kernel<<<dim3(1024 / 64, (BATCH * S2) / 64), 256>>>(H1, 512, W3b, 512, b3b, H2, 1024, 512);
    max_kernel<<<(BATCH * 1024) / 256, 256>>>(H2, out);
}

// round 8
// speedup vs baseline: 2.0460x; 1.1290x over previous
#include <cuda_runtime.h>
#include <cuda_bf16.h>
#include <cstdint>

#define BATCH 16
#define N1 8192
#define S1 512
#define S2 128
#define NS 64

typedef unsigned long long u64;

// ---------------- device scratch ----------------
__device__ float g_xyz1[BATCH * S1 * 3];
__device__ float g_xyz2[BATCH * S2 * 3];
__device__ int   g_idx1[BATCH * S1 * NS];
__device__ int   g_idx2[BATCH * S2 * NS];
__device__ float g_feat1[BATCH * S1 * 128];
__device__ float g_feat2[BATCH * S2 * 256];
__device__ float g_A3[BATCH * S2 * 259];
__device__ float g_H1[BATCH * S2 * 512];
__device__ float g_H2[BATCH * S2 * 1024];

static __device__ __forceinline__ u64 umax64(u64 a, u64 b) { return a > b ? a : b; }

// packed f32x2 helpers (bit-exact: two independent fp32 ops)
static __device__ __forceinline__ u64 pk2(float x, float y) {
    u64 r; asm("mov.b64 %0, {%1, %2};" : "=l"(r) : "f"(x), "f"(y)); return r;
}
static __device__ __forceinline__ float2 upk2(u64 v) {
    float2 f; asm("mov.b64 {%0, %1}, %2;" : "=f"(f.x), "=f"(f.y) : "l"(v)); return f;
}
static __device__ __forceinline__ void ffma2(u64& d, u64 a, u64 b) {
    asm("fma.rn.f32x2 %0, %1, %2, %0;" : "+l"(d) : "l"(a), "l"(b));
}
static __device__ __forceinline__ u64 add2(u64 a, u64 b) {
    u64 r; asm("add.rn.f32x2 %0, %1, %2;" : "=l"(r) : "l"(a), "l"(b)); return r;
}
static __device__ __forceinline__ u64 mul2(u64 a, u64 b) {
    u64 r; asm("mul.rn.f32x2 %0, %1, %2;" : "=l"(r) : "l"(a), "l"(b)); return r;
}

// ---------------- FPS: f32x2-packed distances, cheap argmax tracking ----------------
// Distance tree is bit-identical to the scalar passing version:
//   d = ((dx*dx + dy*dy) + dz*dz), dx = px + (-lx)  (== __fsub_rn)
template<int N, int TPB>
__global__ void __launch_bounds__(TPB) fps_kernel(const float* __restrict__ pts,
                                                  float* __restrict__ outxyz, int NP) {
    constexpr int PPT = N / TPB;
    constexpr int PP2 = PPT / 2;
    constexpr int NW  = TPB / 32;
    extern __shared__ float sh[];
    float* s_pts = sh;                                   // N*3
    u64* s_red = (u64*)(sh + N * 3);                     // 2*NW

    int b = blockIdx.x, tid = threadIdx.x;
    int wid = tid >> 5, lane = tid & 31;
    const float* P = pts + (size_t)b * N * 3;

    u64 px2[PP2], py2[PP2], pz2[PP2];
    float mind[PPT];
#pragma unroll
    for (int p = 0; p < PP2; p++) {
        int i0 = (2 * p) * TPB + tid, i1 = (2 * p + 1) * TPB + tid;
        float x0 = P[i0 * 3 + 0], y0 = P[i0 * 3 + 1], z0 = P[i0 * 3 + 2];
        float x1 = P[i1 * 3 + 0], y1 = P[i1 * 3 + 1], z1 = P[i1 * 3 + 2];
        px2[p] = pk2(x0, x1); py2[p] = pk2(y0, y1); pz2[p] = pk2(z0, z1);
        s_pts[i0 * 3 + 0] = x0; s_pts[i0 * 3 + 1] = y0; s_pts[i0 * 3 + 2] = z0;
        s_pts[i1 * 3 + 0] = x1; s_pts[i1 * 3 + 1] = y1; s_pts[i1 * 3 + 2] = z1;
        mind[2 * p] = 1e10f; mind[2 * p + 1] = 1e10f;
    }
    __syncthreads();

    int last = 0;
    for (int it = 0; it < NP; it++) {
        if (tid == 0) {
            float* o = outxyz + ((size_t)b * NP + it) * 3;
            o[0] = s_pts[last * 3 + 0]; o[1] = s_pts[last * 3 + 1]; o[2] = s_pts[last * 3 + 2];
        }
        float lx = s_pts[last * 3 + 0], ly = s_pts[last * 3 + 1], lz = s_pts[last * 3 + 2];
        u64 nlx = pk2(-lx, -lx), nly = pk2(-ly, -ly), nlz = pk2(-lz, -lz);

        float bestm = -1.0f;
        int bestkey = 0;
#pragma unroll
        for (int p = 0; p < PP2; p++) {
            u64 dx = add2(px2[p], nlx);
            u64 dy = add2(py2[p], nly);
            u64 dz = add2(pz2[p], nlz);
            u64 ss = add2(add2(mul2(dx, dx), mul2(dy, dy)), mul2(dz, dz));
            float2 d = upk2(ss);
            float m0 = fminf(mind[2 * p], d.x);     mind[2 * p] = m0;
            float m1 = fminf(mind[2 * p + 1], d.y); mind[2 * p + 1] = m1;
            if (m0 > bestm) { bestm = m0; bestkey = N - 1 - ((2 * p) * TPB + tid); }
            if (m1 > bestm) { bestm = m1; bestkey = N - 1 - ((2 * p + 1) * TPB + tid); }
        }
        u64 best = ((u64)__float_as_uint(bestm) << 32) | (unsigned)bestkey;
#pragma unroll
        for (int off = 16; off; off >>= 1)
            best = umax64(best, __shfl_down_sync(0xffffffffu, best, off));
        if (lane == 0) s_red[(it & 1) * NW + wid] = best;
        __syncthreads();
        const u64* rr = s_red + (it & 1) * NW;
        u64 a0 = rr[0], a1 = rr[1], a2 = rr[2], a3 = rr[3];
#pragma unroll
        for (int w = 4; w < NW; w += 4) {
            a0 = umax64(a0, rr[w]); a1 = umax64(a1, rr[w + 1]);
            a2 = umax64(a2, rr[w + 2]); a3 = umax64(a3, rr[w + 3]);
        }
        last = N - 1 - (int)(umax64(umax64(a0, a1), umax64(a2, a3)) & 0xffffffffu);
    }
}

// ---------------- ball query ----------------
__global__ void ball_query_kernel(const float* __restrict__ pts,
                                  const float* __restrict__ centers,
                                  int* __restrict__ outidx,
                                  int N, int S, int total, float r2) {
    int gw = (blockIdx.x * blockDim.x + threadIdx.x) >> 5;
    int lane = threadIdx.x & 31;
    if (gw >= total) return;
    int b = gw / S;
    const float* C = centers + (size_t)gw * 3;
    float cx = C[0], cy = C[1], cz = C[2];
    float cn = __fadd_rn(__fadd_rn(__fmul_rn(cx, cx), __fmul_rn(cy, cy)), __fmul_rn(cz, cz));
    const float* P = pts + (size_t)b * N * 3;
    int* out = outidx + (size_t)gw * NS;

    int cnt = 0, firstIdx = -1;
    for (int base = 0; base < N; base += 32) {
        int i = base + lane;
        float qx = P[i * 3 + 0], qy = P[i * 3 + 1], qz = P[i * 3 + 2];
        float pn = __fadd_rn(__fadd_rn(__fmul_rn(qx, qx), __fmul_rn(qy, qy)), __fmul_rn(qz, qz));
        float dt = __fadd_rn(__fadd_rn(__fmul_rn(cx, qx), __fmul_rn(cy, qy)), __fmul_rn(cz, qz));
        float d2 = __fsub_rn(__fadd_rn(cn, pn), __fmul_rn(2.0f, dt));
        unsigned m = __ballot_sync(0xffffffffu, d2 < r2);
        if (lane == 0) {
            while (m && cnt < NS) {
                int p = __ffs(m) - 1;
                m &= m - 1;
                if (firstIdx < 0) firstIdx = base + p;
                out[cnt++] = base + p;
            }
        }
        cnt = __shfl_sync(0xffffffffu, cnt, 0);
        if (cnt >= NS) break;
    }
    if (lane == 0) {
        int fill = (cnt == 0) ? (N - 1) : firstIdx;
        for (int j = cnt; j < NS; j++) out[j] = fill;
    }
}

// ---------------- SA1: group + MLP(3->64->128) + maxpool, FFMA2-tiled ----------------
__global__ void __launch_bounds__(128) sa1_kernel(const float* __restrict__ x,
                                                  const float* __restrict__ cxyz,
                                                  const int* __restrict__ idx,
                                                  const float* __restrict__ W1a,
                                                  const float* __restrict__ b1a,
                                                  const float* __restrict__ W1b,
                                                  const float* __restrict__ b1b,
                                                  float* __restrict__ feat) {
    extern __shared__ float s1[];
    float* s_hT   = s1;                  // [c=64][k pad 68]
    float* s_wT   = s_hT + 64 * 68;      // [c=64][o pad 132]
    float* s_m    = s_wT + 64 * 132;     // [8][128] (also W1a staging: 192 floats)
    float* s_g    = s_m + 8 * 128;       // [64][4]
    float* s_bias = s_g + 64 * 4;        // [64]

    int gblk = blockIdx.x;
    int b = gblk >> 9;
    int t = threadIdx.x;

    float cx = cxyz[gblk * 3 + 0], cy = cxyz[gblk * 3 + 1], cz = cxyz[gblk * 3 + 2];
    if (t < 64) {
        int i = idx[(size_t)gblk * NS + t];
        const float* p = x + ((size_t)b * N1 + i) * 3;
        s_g[t * 4 + 0] = p[0] - cx;
        s_g[t * 4 + 1] = p[1] - cy;
        s_g[t * 4 + 2] = p[2] - cz;
        s_bias[t] = b1a[t];
    }
    for (int e = t; e < 64 * 3; e += 128) s_m[e] = W1a[e];
    for (int e = t; e < 128 * 64; e += 128) {                       // W1b^T
        int o = e >> 6, c = e & 63;
        s_wT[c * 132 + o] = W1b[e];
    }
    __syncthreads();

    // layer1 -> s_hT[c][k]
    for (int e = t; e < 64 * 64; e += 128) {
        int k = e >> 6, o1 = e & 63;
        float v = s_g[k * 4 + 0] * s_m[o1 * 3 + 0] + s_g[k * 4 + 1] * s_m[o1 * 3 + 1]
                + s_g[k * 4 + 2] * s_m[o1 * 3 + 2] + s_bias[o1];
        s_hT[o1 * 68 + k] = fmaxf(v, 0.f);
    }
    __syncthreads();

    // layer2: C[k=64][o=128], 8k x 8o per thread, k paired for FFMA2
    int kr = t & 7, oc = t >> 3;   // oc 0..15
    u64 acc[4][8];
#pragma unroll
    for (int i = 0; i < 4; i++)
#pragma unroll
        for (int j = 0; j < 8; j++) acc[i][j] = 0ull;

    for (int c = 0; c < 64; c++) {
        const float* hr = s_hT + c * 68;
        float4 ha = *(const float4*)(hr + kr * 4);
        float4 hb = *(const float4*)(hr + 32 + kr * 4);
        u64 hp[4] = { pk2(ha.x, ha.y), pk2(ha.z, ha.w), pk2(hb.x, hb.y), pk2(hb.z, hb.w) };
        const float* wr = s_wT + c * 132;
        float4 wa = *(const float4*)(wr + oc * 4);
        float4 wb = *(const float4*)(wr + 64 + oc * 4);
        float wv[8] = { wa.x, wa.y, wa.z, wa.w, wb.x, wb.y, wb.z, wb.w };
#pragma unroll
        for (int oo = 0; oo < 8; oo++) {
            u64 wd = pk2(wv[oo], wv[oo]);
#pragma unroll
            for (int kp = 0; kp < 4; kp++) ffma2(acc[kp][oo], hp[kp], wd);
        }
    }
#pragma unroll
    for (int oo = 0; oo < 8; oo++) {
        int o = (oo < 4) ? (oc * 4 + oo) : (64 + oc * 4 + (oo - 4));
        float bias = b1b[o];
        float best = 0.f;
#pragma unroll
        for (int kp = 0; kp < 4; kp++) {
            float2 v = upk2(acc[kp][oo]);
            best = fmaxf(best, fmaxf(v.x + bias, 0.f));
            best = fmaxf(best, fmaxf(v.y + bias, 0.f));
        }
        s_m[kr * 128 + o] = best;
    }
    __syncthreads();
    if (t < 128) {
        float r = s_m[t];
#pragma unroll
        for (int w = 1; w < 8; w++) r = fmaxf(r, s_m[w * 128 + t]);
        feat[(size_t)gblk * 128 + t] = r;
    }
}

// ---------------- SA2: group + MLP(131->128->256) + maxpool, FFMA2-tiled ----------------
__global__ void __launch_bounds__(256) sa2_kernel(const float* __restrict__ xyz1,
                                                  const float* __restrict__ cxyz,
                                                  const int* __restrict__ idx,
                                                  const float* __restrict__ feat1,
                                                  const float* __restrict__ W2a,
                                                  const float* __restrict__ b2a,
                                                  const float* __restrict__ W2b,
                                                  const float* __restrict__ b2b,
                                                  float* __restrict__ feat2) {
    extern __shared__ float s2[];
    float* s_h1T = s2;                       // [o=128][k pad 68]
    float* s_gT  = s2 + 128 * 68;            // [c=131][k pad 68]
    float* s_waT = s_gT + 131 * 68;          // [c=131][o pad 132]
    float* s_wbT = s2 + 128 * 68;            // [c=128][o pad 260]  (reuses gT/waT)
    float* s_m   = s_wbT + 128 * 260;        // [8][256]

    int gblk = blockIdx.x;
    int b = gblk >> 7;
    int t = threadIdx.x;
    float cx = cxyz[gblk * 3 + 0], cy = cxyz[gblk * 3 + 1], cz = cxyz[gblk * 3 + 2];

    // stage A: gather -> s_gT[c][k], 4 threads per k
    {
        int k = t >> 2, sub = t & 3;
        int i = idx[(size_t)gblk * NS + k];
        if (sub < 3) {
            float pv = xyz1[((size_t)b * S1 + i) * 3 + sub];
            s_gT[sub * 68 + k] = pv - (sub == 0 ? cx : (sub == 1 ? cy : cz));
        }
        const float* f = feat1 + ((size_t)b * S1 + i) * 128;
        for (int c = sub; c < 128; c += 4)
            s_gT[(3 + c) * 68 + k] = f[c];
    }
    // W2a^T
    for (int e = t; e < 128 * 131; e += 256) {
        int o = e / 131, c = e - o * 131;
        s_waT[c * 132 + o] = W2a[e];
    }
    __syncthreads();

    int kr = t & 7, oc = t >> 3;  // oc 0..31

    // stage B: h1[k=64][o=128], 8k x 4o per thread
    {
        u64 acc[4][4];
#pragma unroll
        for (int i = 0; i < 4; i++)
#pragma unroll
            for (int j = 0; j < 4; j++) acc[i][j] = 0ull;
        for (int c = 0; c < 131; c++) {
            const float* g = s_gT + c * 68;
            float4 ha = *(const float4*)(g + kr * 4);
            float4 hb = *(const float4*)(g + 32 + kr * 4);
            u64 hp[4] = { pk2(ha.x, ha.y), pk2(ha.z, ha.w), pk2(hb.x, hb.y), pk2(hb.z, hb.w) };
            float4 wv = *(const float4*)(s_waT + c * 132 + oc * 4);
            float wvv[4] = { wv.x, wv.y, wv.z, wv.w };
#pragma unroll
            for (int oo = 0; oo < 4; oo++) {
                u64 wd = pk2(wvv[oo], wvv[oo]);
#pragma unroll
                for (int kp = 0; kp < 4; kp++) ffma2(acc[kp][oo], hp[kp], wd);
            }
        }
#pragma unroll
        for (int oo = 0; oo < 4; oo++) {
            int o = oc * 4 + oo;
            float bias = b2a[o];
#pragma unroll
            for (int kp = 0; kp < 4; kp++) {
                int k0 = (kp < 2) ? (kr * 4 + kp * 2) : (32 + kr * 4 + (kp - 2) * 2);
                float2 v = upk2(acc[kp][oo]);
                float2 r = make_float2(fmaxf(v.x + bias, 0.f), fmaxf(v.y + bias, 0.f));
                *(float2*)(s_h1T + o * 68 + k0) = r;
            }
        }
    }
    __syncthreads();

    // load W2b^T (overwrites gT/waT region)
    for (int e = t; e < 256 * 128; e += 256) {
        int o = e >> 7, c = e & 127;
        s_wbT[c * 260 + o] = W2b[e];
    }
    __syncthreads();

    // stage C: out[k=64][o=256], 8k x 8o per thread, max over k
    {
        u64 acc[4][8];
#pragma unroll
        for (int i = 0; i < 4; i++)
#pragma unroll
            for (int j = 0; j < 8; j++) acc[i][j] = 0ull;
        for (int c = 0; c < 128; c++) {
            const float* h = s_h1T + c * 68;
            float4 ha = *(const float4*)(h + kr * 4);
            float4 hb = *(const float4*)(h + 32 + kr * 4);
            u64 hp[4] = { pk2(ha.x, ha.y), pk2(ha.z, ha.w), pk2(hb.x, hb.y), pk2(hb.z, hb.w) };
            const float* w = s_wbT + c * 260;
            float4 wa = *(const float4*)(w + oc * 4);
            float4 wb = *(const float4*)(w + 128 + oc * 4);
            float wv[8] = { wa.x, wa.y, wa.z, wa.w, wb.x, wb.y, wb.z, wb.w };
#pragma unroll
            for (int oo = 0; oo < 8; oo++) {
                u64 wd = pk2(wv[oo], wv[oo]);
#pragma unroll
                for (int kp = 0; kp < 4; kp++) ffma2(acc[kp][oo], hp[kp], wd);
            }
        }
#pragma unroll
        for (int oo = 0; oo < 8; oo++) {
            int o = (oo < 4) ? (oc * 4 + oo) : (128 + oc * 4 + (oo - 4));
            float bias = b2b[o];
            float best = 0.f;
#pragma unroll
            for (int kp = 0; kp < 4; kp++) {
                float2 v = upk2(acc[kp][oo]);
                best = fmaxf(best, fmaxf(v.x + bias, 0.f));
                best = fmaxf(best, fmaxf(v.y + bias, 0.f));
            }
            s_m[kr * 256 + o] = best;
        }
    }
    __syncthreads();
    {
        float r = s_m[t];
#pragma unroll
        for (int w = 1; w < 8; w++) r = fmaxf(r, s_m[w * 256 + t]);
        feat2[(size_t)gblk * 256 + t] = r;
    }
}

// ---------------- concat xyz2 + feat2 -> A3 [2048][259] ----------------
__global__ void concat_kernel(const float* __restrict__ xyz2,
                              const float* __restrict__ feat2,
                              float* __restrict__ A3) {
    int e = blockIdx.x * blockDim.x + threadIdx.x;
    if (e >= BATCH * S2 * 259) return;
    int r = e / 259, c = e - r * 259;
    A3[e] = (c < 3) ? xyz2[r * 3 + c] : feat2[(size_t)r * 256 + (c - 3)];
}

// ---------------- tiled GEMM: C = relu(A[M,K] * W[N,K]^T + bias), FFMA2 ----------------
__global__ void __launch_bounds__(256) gemm_relu_kernel(const float* __restrict__ A, int lda,
                                                        const float* __restrict__ W, int ldw,
                                                        const float* __restrict__ bias,
                                                        float* __restrict__ C, int ldc, int K) {
    __shared__ float As[16][68];
    __shared__ float Ws[16][68];
    int bm = blockIdx.y * 64, bn = blockIdx.x * 64;
    int t = threadIdx.x;
    int tx = t & 15, ty = t >> 4;

    u64 acc[2][4];
#pragma unroll
    for (int i = 0; i < 2; i++)
#pragma unroll
        for (int j = 0; j < 4; j++) acc[i][j] = 0ull;

    for (int k0 = 0; k0 < K; k0 += 16) {
#pragma unroll
        for (int l = 0; l < 4; l++) {
            int e = t + l * 256;
            int m = e >> 4, kk = e & 15;
            int gk = k0 + kk;
            As[kk][m] = (gk < K) ? A[(size_t)(bm + m) * lda + gk] : 0.f;
        }
#pragma unroll
        for (int l = 0; l < 4; l++) {
            int e = t + l * 256;
            int n = e >> 4, kk = e & 15;
            int gk = k0 + kk;
            Ws[kk][n] = (gk < K) ? W[(size_t)(bn + n) * ldw + gk] : 0.f;
        }
        __syncthreads();
#pragma unroll
        for (int kk = 0; kk < 16; kk++) {
            float4 av = *(const float4*)(&As[kk][ty * 4]);
            float4 wv = *(const float4*)(&Ws[kk][tx * 4]);
            u64 ap[2] = { pk2(av.x, av.y), pk2(av.z, av.w) };
            float wvv[4] = { wv.x, wv.y, wv.z, wv.w };
#pragma unroll
            for (int j = 0; j < 4; j++) {
                u64 wd = pk2(wvv[j], wvv[j]);
                ffma2(acc[0][j], ap[0], wd);
                ffma2(acc[1][j], ap[1], wd);
            }
        }
        __syncthreads();
    }
#pragma unroll
    for (int ip = 0; ip < 2; ip++) {
#pragma unroll
        for (int j = 0; j < 4; j++) {
            float2 v = upk2(acc[ip][j]);
            int col = bn + tx * 4 + j;
            float bb = bias[col];
            int row0 = bm + ty * 4 + ip * 2;
            C[(size_t)row0 * ldc + col]       = fmaxf(v.x + bb, 0.f);
            C[(size_t)(row0 + 1) * ldc + col] = fmaxf(v.y + bb, 0.f);
        }
    }
}

// ---------------- final max over 128 rows per batch ----------------
__global__ void max_kernel(const float* __restrict__ H, float* __restrict__ out) {
    int e = blockIdx.x * blockDim.x + threadIdx.x;
    int b = e >> 10, o = e & 1023;
    const float* p = H + (size_t)b * S2 * 1024 + o;
    float m = p[0];
#pragma unroll 8
    for (int k = 1; k < S2; k++) m = fmaxf(m, p[(size_t)k * 1024]);
    out[e] = m;
}

// ---------------- launch ----------------
extern "C" void kernel_launch(void* const* d_in, const int* in_sizes, int n_in,
                              void* d_out, int out_size) {
    const float* x   = (const float*)d_in[0];
    const float* W1a = (const float*)d_in[1];
    const float* b1a = (const float*)d_in[2];
    const float* W1b = (const float*)d_in[3];
    const float* b1b = (const float*)d_in[4];
    const float* W2a = (const float*)d_in[5];
    const float* b2a = (const float*)d_in[6];
    const float* W2b = (const float*)d_in[7];
    const float* b2b = (const float*)d_in[8];
    const float* W3a = (const float*)d_in[9];
    const float* b3a = (const float*)d_in[10];
    const float* W3b = (const float*)d_in[11];
    const float* b3b = (const float*)d_in[12];
    float* out = (float*)d_out;

    float *xyz1, *xyz2, *feat1, *feat2, *A3, *H1, *H2;
    int *idx1, *idx2;
    cudaGetSymbolAddress((void**)&xyz1, g_xyz1);
    cudaGetSymbolAddress((void**)&xyz2, g_xyz2);
    cudaGetSymbolAddress((void**)&idx1, g_idx1);
    cudaGetSymbolAddress((void**)&idx2, g_idx2);
    cudaGetSymbolAddress((void**)&feat1, g_feat1);
    cudaGetSymbolAddress((void**)&feat2, g_feat2);
    cudaGetSymbolAddress((void**)&A3, g_A3);
    cudaGetSymbolAddress((void**)&H1, g_H1);
    cudaGetSymbolAddress((void**)&H2, g_H2);

    // side stream + events for fps2/bq2 overlap (created once, outside capture:
    // first harness call is the uncaptured correctness run)
    static cudaStream_t sAux = nullptr;
    static cudaEvent_t evFork = nullptr, evJoin = nullptr;
    if (sAux == nullptr) {
        cudaStreamCreateWithFlags(&sAux, cudaStreamNonBlocking);
        cudaEventCreateWithFlags(&evFork, cudaEventDisableTiming);
        cudaEventCreateWithFlags(&evJoin, cudaEventDisableTiming);
    }

    const float r2_1 = (float)(0.2 * 0.2);
    const float r2_2 = (float)(0.4 * 0.4);

    // SA1 sampling
    size_t fps1_smem = (size_t)N1 * 3 * sizeof(float) + 2 * 16 * sizeof(u64);
    cudaFuncSetAttribute((const void*)fps_kernel<N1, 512>,
                         cudaFuncAttributeMaxDynamicSharedMemorySize, (int)fps1_smem);
    fps_kernel<N1, 512><<<BATCH, 512, fps1_smem>>>(x, xyz1, S1);

    // fork: fps2+bq2 depend only on xyz1 -> run on side stream under bq1+sa1
    cudaEventRecord(evFork, 0);
    cudaStreamWaitEvent(sAux, evFork, 0);

    ball_query_kernel<<<(BATCH * S1) / 8, 256>>>(x, xyz1, idx1, N1, S1, BATCH * S1, r2_1);
    size_t sa1_smem = (64 * 68 + 64 * 132 + 8 * 128 + 64 * 4 + 64) * sizeof(float);
    cudaFuncSetAttribute((const void*)sa1_kernel,
                         cudaFuncAttributeMaxDynamicSharedMemorySize, (int)sa1_smem);
    sa1_kernel<<<BATCH * S1, 128, sa1_smem>>>(x, xyz1, idx1, W1a, b1a, W1b, b1b, feat1);

    size_t fps2_smem = (size_t)S1 * 3 * sizeof(float) + 2 * 8 * sizeof(u64);
    fps_kernel<S1, 256><<<BATCH, 256, fps2_smem, sAux>>>(xyz1, xyz2, S2);
    ball_query_kernel<<<(BATCH * S2) / 8, 256, 0, sAux>>>(xyz1, xyz2, idx2, S1, S2, BATCH * S2, r2_2);
    cudaEventRecord(evJoin, sAux);
    cudaStreamWaitEvent(0, evJoin, 0);

    // SA2
    size_t sa2_smem = (size_t)(128 * 68 + 128 * 260 + 8 * 256) * sizeof(float);
    cudaFuncSetAttribute((const void*)sa2_kernel,
                         cudaFuncAttributeMaxDynamicSharedMemorySize, (int)sa2_smem);
    sa2_kernel<<<BATCH * S2, 256, sa2_smem>>>(xyz1, xyz2, idx2, feat1,
                                              W2a, b2a, W2b, b2b, feat2);

    // Head
    concat_kernel<<<(BATCH * S2 * 259 + 255) / 256, 256>>>(xyz2, feat2, A3);
    gemm_relu_kernel<<<dim3(512 / 64, (BATCH * S2) / 64), 256>>>(A3, 259, W3a, 259, b3a, H1, 512, 259);
    gemm_relu_kernel<<<dim3(1024 / 64, (BATCH * S2) / 64), 256>>>(H1, 512, W3b, 512, b3b, H2, 1024, 512);
    max_kernel<<<(BATCH * 1024) / 256, 256>>>(H2, out);
}

// round 11
// speedup vs baseline: 2.2778x; 1.1133x over previous
#include <cuda_runtime.h>
#include <cuda_bf16.h>
#include <cstdint>

#define BATCH 16
#define N1 8192
#define S1 512
#define S2 128
#define NS 64

typedef unsigned long long u64;

// ---------------- device scratch ----------------
__device__ float g_xyz1[BATCH * S1 * 3];
__device__ float g_xyz2[BATCH * S2 * 3];
__device__ int   g_idx1[BATCH * S1 * NS];
__device__ int   g_idx2[BATCH * S2 * NS];
__device__ float g_feat1[BATCH * S1 * 128];
__device__ float g_feat2[BATCH * S2 * 256];
__device__ float g_A3[BATCH * S2 * 259];
__device__ float g_H1[BATCH * S2 * 512];

static __device__ __forceinline__ u64 umax64(u64 a, u64 b) { return a > b ? a : b; }

// packed f32x2 helpers (bit-exact: two independent fp32 ops)
static __device__ __forceinline__ u64 pk2(float x, float y) {
    u64 r; asm("mov.b64 %0, {%1, %2};" : "=l"(r) : "f"(x), "f"(y)); return r;
}
static __device__ __forceinline__ float2 upk2(u64 v) {
    float2 f; asm("mov.b64 {%0, %1}, %2;" : "=f"(f.x), "=f"(f.y) : "l"(v)); return f;
}
static __device__ __forceinline__ void ffma2(u64& d, u64 a, u64 b) {
    asm("fma.rn.f32x2 %0, %1, %2, %0;" : "+l"(d) : "l"(a), "l"(b));
}
static __device__ __forceinline__ u64 add2(u64 a, u64 b) {
    u64 r; asm("add.rn.f32x2 %0, %1, %2;" : "=l"(r) : "l"(a), "l"(b)); return r;
}
static __device__ __forceinline__ u64 mul2(u64 a, u64 b) {
    u64 r; asm("mul.rn.f32x2 %0, %1, %2;" : "=l"(r) : "l"(a), "l"(b)); return r;
}

// ---------------- FPS: f32x2-packed distances, cheap argmax tracking ----------------
template<int N, int TPB>
__global__ void __launch_bounds__(TPB) fps_kernel(const float* __restrict__ pts,
                                                  float* __restrict__ outxyz, int NP) {
    constexpr int PPT = N / TPB;
    constexpr int PP2 = PPT / 2;
    constexpr int NW  = TPB / 32;
    extern __shared__ float sh[];
    float* s_pts = sh;                                   // N*3
    u64* s_red = (u64*)(sh + N * 3);                     // 2*NW

    int b = blockIdx.x, tid = threadIdx.x;
    int wid = tid >> 5, lane = tid & 31;
    const float* P = pts + (size_t)b * N * 3;

    u64 px2[PP2], py2[PP2], pz2[PP2];
    float mind[PPT];
#pragma unroll
    for (int p = 0; p < PP2; p++) {
        int i0 = (2 * p) * TPB + tid, i1 = (2 * p + 1) * TPB + tid;
        float x0 = P[i0 * 3 + 0], y0 = P[i0 * 3 + 1], z0 = P[i0 * 3 + 2];
        float x1 = P[i1 * 3 + 0], y1 = P[i1 * 3 + 1], z1 = P[i1 * 3 + 2];
        px2[p] = pk2(x0, x1); py2[p] = pk2(y0, y1); pz2[p] = pk2(z0, z1);
        s_pts[i0 * 3 + 0] = x0; s_pts[i0 * 3 + 1] = y0; s_pts[i0 * 3 + 2] = z0;
        s_pts[i1 * 3 + 0] = x1; s_pts[i1 * 3 + 1] = y1; s_pts[i1 * 3 + 2] = z1;
        mind[2 * p] = 1e10f; mind[2 * p + 1] = 1e10f;
    }
    __syncthreads();

    int last = 0;
    for (int it = 0; it < NP; it++) {
        if (tid == 0) {
            float* o = outxyz + ((size_t)b * NP + it) * 3;
            o[0] = s_pts[last * 3 + 0]; o[1] = s_pts[last * 3 + 1]; o[2] = s_pts[last * 3 + 2];
        }
        float lx = s_pts[last * 3 + 0], ly = s_pts[last * 3 + 1], lz = s_pts[last * 3 + 2];
        u64 nlx = pk2(-lx, -lx), nly = pk2(-ly, -ly), nlz = pk2(-lz, -lz);

        float bestm = -1.0f;
        int bestkey = 0;
#pragma unroll
        for (int p = 0; p < PP2; p++) {
            u64 dx = add2(px2[p], nlx);
            u64 dy = add2(py2[p], nly);
            u64 dz = add2(pz2[p], nlz);
            u64 ss = add2(add2(mul2(dx, dx), mul2(dy, dy)), mul2(dz, dz));
            float2 d = upk2(ss);
            float m0 = fminf(mind[2 * p], d.x);     mind[2 * p] = m0;
            float m1 = fminf(mind[2 * p + 1], d.y); mind[2 * p + 1] = m1;
            if (m0 > bestm) { bestm = m0; bestkey = N - 1 - ((2 * p) * TPB + tid); }
            if (m1 > bestm) { bestm = m1; bestkey = N - 1 - ((2 * p + 1) * TPB + tid); }
        }
        u64 best = ((u64)__float_as_uint(bestm) << 32) | (unsigned)bestkey;
#pragma unroll
        for (int off = 16; off; off >>= 1)
            best = umax64(best, __shfl_down_sync(0xffffffffu, best, off));
        if (lane == 0) s_red[(it & 1) * NW + wid] = best;
        __syncthreads();
        const u64* rr = s_red + (it & 1) * NW;
        u64 a0 = rr[0], a1 = rr[1], a2 = rr[2], a3 = rr[3];
#pragma unroll
        for (int w = 4; w < NW; w += 4) {
            a0 = umax64(a0, rr[w]); a1 = umax64(a1, rr[w + 1]);
            a2 = umax64(a2, rr[w + 2]); a3 = umax64(a3, rr[w + 3]);
        }
        last = N - 1 - (int)(umax64(umax64(a0, a1), umax64(a2, a3)) & 0xffffffffu);
    }
}

// ---------------- ball query ----------------
__global__ void ball_query_kernel(const float* __restrict__ pts,
                                  const float* __restrict__ centers,
                                  int* __restrict__ outidx,
                                  int N, int S, int total, float r2) {
    int gw = (blockIdx.x * blockDim.x + threadIdx.x) >> 5;
    int lane = threadIdx.x & 31;
    if (gw >= total) return;
    int b = gw / S;
    const float* C = centers + (size_t)gw * 3;
    float cx = C[0], cy = C[1], cz = C[2];
    float cn = __fadd_rn(__fadd_rn(__fmul_rn(cx, cx), __fmul_rn(cy, cy)), __fmul_rn(cz, cz));
    const float* P = pts + (size_t)b * N * 3;
    int* out = outidx + (size_t)gw * NS;

    int cnt = 0, firstIdx = -1;
    for (int base = 0; base < N; base += 32) {
        int i = base + lane;
        float qx = P[i * 3 + 0], qy = P[i * 3 + 1], qz = P[i * 3 + 2];
        float pn = __fadd_rn(__fadd_rn(__fmul_rn(qx, qx), __fmul_rn(qy, qy)), __fmul_rn(qz, qz));
        float dt = __fadd_rn(__fadd_rn(__fmul_rn(cx, qx), __fmul_rn(cy, qy)), __fmul_rn(cz, qz));
        float d2 = __fsub_rn(__fadd_rn(cn, pn), __fmul_rn(2.0f, dt));
        unsigned m = __ballot_sync(0xffffffffu, d2 < r2);
        if (lane == 0) {
            while (m && cnt < NS) {
                int p = __ffs(m) - 1;
                m &= m - 1;
                if (firstIdx < 0) firstIdx = base + p;
                out[cnt++] = base + p;
            }
        }
        cnt = __shfl_sync(0xffffffffu, cnt, 0);
        if (cnt >= NS) break;
    }
    if (lane == 0) {
        int fill = (cnt == 0) ? (N - 1) : firstIdx;
        for (int j = cnt; j < NS; j++) out[j] = fill;
    }
}

// ---------------- SA1: group + MLP(3->64->128) + maxpool, FFMA2-tiled ----------------
__global__ void __launch_bounds__(128) sa1_kernel(const float* __restrict__ x,
                                                  const float* __restrict__ cxyz,
                                                  const int* __restrict__ idx,
                                                  const float* __restrict__ W1a,
                                                  const float* __restrict__ b1a,
                                                  const float* __restrict__ W1b,
                                                  const float* __restrict__ b1b,
                                                  float* __restrict__ feat) {
    extern __shared__ float s1[];
    float* s_hT   = s1;                  // [c=64][k pad 68]
    float* s_wT   = s_hT + 64 * 68;      // [c=64][o pad 132]
    float* s_m    = s_wT + 64 * 132;     // [8][128] (also W1a staging: 192 floats)
    float* s_g    = s_m + 8 * 128;       // [64][4]
    float* s_bias = s_g + 64 * 4;        // [64]

    int gblk = blockIdx.x;
    int b = gblk >> 9;
    int t = threadIdx.x;

    float cx = cxyz[gblk * 3 + 0], cy = cxyz[gblk * 3 + 1], cz = cxyz[gblk * 3 + 2];
    if (t < 64) {
        int i = idx[(size_t)gblk * NS + t];
        const float* p = x + ((size_t)b * N1 + i) * 3;
        s_g[t * 4 + 0] = p[0] - cx;
        s_g[t * 4 + 1] = p[1] - cy;
        s_g[t * 4 + 2] = p[2] - cz;
        s_bias[t] = b1a[t];
    }
    for (int e = t; e < 64 * 3; e += 128) s_m[e] = W1a[e];
    for (int e = t; e < 128 * 64; e += 128) {                       // W1b^T
        int o = e >> 6, c = e & 63;
        s_wT[c * 132 + o] = W1b[e];
    }
    __syncthreads();

    // layer1 -> s_hT[c][k]
    for (int e = t; e < 64 * 64; e += 128) {
        int k = e >> 6, o1 = e & 63;
        float v = s_g[k * 4 + 0] * s_m[o1 * 3 + 0] + s_g[k * 4 + 1] * s_m[o1 * 3 + 1]
                + s_g[k * 4 + 2] * s_m[o1 * 3 + 2] + s_bias[o1];
        s_hT[o1 * 68 + k] = fmaxf(v, 0.f);
    }
    __syncthreads();

    // layer2: C[k=64][o=128], 8k x 8o per thread, k paired for FFMA2
    int kr = t & 7, oc = t >> 3;   // oc 0..15
    u64 acc[4][8];
#pragma unroll
    for (int i = 0; i < 4; i++)
#pragma unroll
        for (int j = 0; j < 8; j++) acc[i][j] = 0ull;

    for (int c = 0; c < 64; c++) {
        const float* hr = s_hT + c * 68;
        float4 ha = *(const float4*)(hr + kr * 4);
        float4 hb = *(const float4*)(hr + 32 + kr * 4);
        u64 hp[4] = { pk2(ha.x, ha.y), pk2(ha.z, ha.w), pk2(hb.x, hb.y), pk2(hb.z, hb.w) };
        const float* wr = s_wT + c * 132;
        float4 wa = *(const float4*)(wr + oc * 4);
        float4 wb = *(const float4*)(wr + 64 + oc * 4);
        float wv[8] = { wa.x, wa.y, wa.z, wa.w, wb.x, wb.y, wb.z, wb.w };
#pragma unroll
        for (int oo = 0; oo < 8; oo++) {
            u64 wd = pk2(wv[oo], wv[oo]);
#pragma unroll
            for (int kp = 0; kp < 4; kp++) ffma2(acc[kp][oo], hp[kp], wd);
        }
    }
#pragma unroll
    for (int oo = 0; oo < 8; oo++) {
        int o = (oo < 4) ? (oc * 4 + oo) : (64 + oc * 4 + (oo - 4));
        float bias = b1b[o];
        float best = 0.f;
#pragma unroll
        for (int kp = 0; kp < 4; kp++) {
            float2 v = upk2(acc[kp][oo]);
            best = fmaxf(best, fmaxf(v.x + bias, 0.f));
            best = fmaxf(best, fmaxf(v.y + bias, 0.f));
        }
        s_m[kr * 128 + o] = best;
    }
    __syncthreads();
    if (t < 128) {
        float r = s_m[t];
#pragma unroll
        for (int w = 1; w < 8; w++) r = fmaxf(r, s_m[w * 128 + t]);
        feat[(size_t)gblk * 128 + t] = r;
    }
}

// ---------------- SA2: group + MLP(131->128->256) + maxpool, FFMA2-tiled ----------------
__global__ void __launch_bounds__(256) sa2_kernel(const float* __restrict__ xyz1,
                                                  const float* __restrict__ cxyz,
                                                  const int* __restrict__ idx,
                                                  const float* __restrict__ feat1,
                                                  const float* __restrict__ W2a,
                                                  const float* __restrict__ b2a,
                                                  const float* __restrict__ W2b,
                                                  const float* __restrict__ b2b,
                                                  float* __restrict__ feat2) {
    extern __shared__ float s2[];
    float* s_h1T = s2;                       // [o=128][k pad 68]
    float* s_gT  = s2 + 128 * 68;            // [c=131][k pad 68]
    float* s_waT = s_gT + 131 * 68;          // [c=131][o pad 132]
    float* s_wbT = s2 + 128 * 68;            // [c=128][o pad 260]  (reuses gT/waT)
    float* s_m   = s_wbT + 128 * 260;        // [8][256]

    int gblk = blockIdx.x;
    int b = gblk >> 7;
    int t = threadIdx.x;
    float cx = cxyz[gblk * 3 + 0], cy = cxyz[gblk * 3 + 1], cz = cxyz[gblk * 3 + 2];

    // stage A: gather -> s_gT[c][k], 4 threads per k
    {
        int k = t >> 2, sub = t & 3;
        int i = idx[(size_t)gblk * NS + k];
        if (sub < 3) {
            float pv = xyz1[((size_t)b * S1 + i) * 3 + sub];
            s_gT[sub * 68 + k] = pv - (sub == 0 ? cx : (sub == 1 ? cy : cz));
        }
        const float* f = feat1 + ((size_t)b * S1 + i) * 128;
        for (int c = sub; c < 128; c += 4)
            s_gT[(3 + c) * 68 + k] = f[c];
    }
    // W2a^T
    for (int e = t; e < 128 * 131; e += 256) {
        int o = e / 131, c = e - o * 131;
        s_waT[c * 132 + o] = W2a[e];
    }
    __syncthreads();

    int kr = t & 7, oc = t >> 3;  // oc 0..31

    // stage B: h1[k=64][o=128], 8k x 4o per thread
    {
        u64 acc[4][4];
#pragma unroll
        for (int i = 0; i < 4; i++)
#pragma unroll
            for (int j = 0; j < 4; j++) acc[i][j] = 0ull;
        for (int c = 0; c < 131; c++) {
            const float* g = s_gT + c * 68;
            float4 ha = *(const float4*)(g + kr * 4);
            float4 hb = *(const float4*)(g + 32 + kr * 4);
            u64 hp[4] = { pk2(ha.x, ha.y), pk2(ha.z, ha.w), pk2(hb.x, hb.y), pk2(hb.z, hb.w) };
            float4 wv = *(const float4*)(s_waT + c * 132 + oc * 4);
            float wvv[4] = { wv.x, wv.y, wv.z, wv.w };
#pragma unroll
            for (int oo = 0; oo < 4; oo++) {
                u64 wd = pk2(wvv[oo], wvv[oo]);
#pragma unroll
                for (int kp = 0; kp < 4; kp++) ffma2(acc[kp][oo], hp[kp], wd);
            }
        }
#pragma unroll
        for (int oo = 0; oo < 4; oo++) {
            int o = oc * 4 + oo;
            float bias = b2a[o];
#pragma unroll
            for (int kp = 0; kp < 4; kp++) {
                int k0 = (kp < 2) ? (kr * 4 + kp * 2) : (32 + kr * 4 + (kp - 2) * 2);
                float2 v = upk2(acc[kp][oo]);
                float2 r = make_float2(fmaxf(v.x + bias, 0.f), fmaxf(v.y + bias, 0.f));
                *(float2*)(s_h1T + o * 68 + k0) = r;
            }
        }
    }
    __syncthreads();

    // load W2b^T (overwrites gT/waT region)
    for (int e = t; e < 256 * 128; e += 256) {
        int o = e >> 7, c = e & 127;
        s_wbT[c * 260 + o] = W2b[e];
    }
    __syncthreads();

    // stage C: out[k=64][o=256], 8k x 8o per thread, max over k
    {
        u64 acc[4][8];
#pragma unroll
        for (int i = 0; i < 4; i++)
#pragma unroll
            for (int j = 0; j < 8; j++) acc[i][j] = 0ull;
        for (int c = 0; c < 128; c++) {
            const float* h = s_h1T + c * 68;
            float4 ha = *(const float4*)(h + kr * 4);
            float4 hb = *(const float4*)(h + 32 + kr * 4);
            u64 hp[4] = { pk2(ha.x, ha.y), pk2(ha.z, ha.w), pk2(hb.x, hb.y), pk2(hb.z, hb.w) };
            const float* w = s_wbT + c * 260;
            float4 wa = *(const float4*)(w + oc * 4);
            float4 wb = *(const float4*)(w + 128 + oc * 4);
            float wv[8] = { wa.x, wa.y, wa.z, wa.w, wb.x, wb.y, wb.z, wb.w };
#pragma unroll
            for (int oo = 0; oo < 8; oo++) {
                u64 wd = pk2(wv[oo], wv[oo]);
#pragma unroll
                for (int kp = 0; kp < 4; kp++) ffma2(acc[kp][oo], hp[kp], wd);
            }
        }
#pragma unroll
        for (int oo = 0; oo < 8; oo++) {
            int o = (oo < 4) ? (oc * 4 + oo) : (128 + oc * 4 + (oo - 4));
            float bias = b2b[o];
            float best = 0.f;
#pragma unroll
            for (int kp = 0; kp < 4; kp++) {
                float2 v = upk2(acc[kp][oo]);
                best = fmaxf(best, fmaxf(v.x + bias, 0.f));
                best = fmaxf(best, fmaxf(v.y + bias, 0.f));
            }
            s_m[kr * 256 + o] = best;
        }
    }
    __syncthreads();
    {
        float r = s_m[t];
#pragma unroll
        for (int w = 1; w < 8; w++) r = fmaxf(r, s_m[w * 256 + t]);
        feat2[(size_t)gblk * 256 + t] = r;
    }
}

// ---------------- concat xyz2 + feat2 -> A3 [2048][259] ----------------
__global__ void concat_kernel(const float* __restrict__ xyz2,
                              const float* __restrict__ feat2,
                              float* __restrict__ A3) {
    int e = blockIdx.x * blockDim.x + threadIdx.x;
    if (e >= BATCH * S2 * 259) return;
    int r = e / 259, c = e - r * 259;
    A3[e] = (c < 3) ? xyz2[r * 3 + c] : feat2[(size_t)r * 256 + (c - 3)];
}

// ---------------- zero-init output ----------------
__global__ void init_out_kernel(float* __restrict__ out) {
    int e = blockIdx.x * blockDim.x + threadIdx.x;
    if (e < BATCH * 1024) out[e] = 0.f;
}

// ---------------- tiled GEMM: C = relu(A*W^T + bias), FFMA2 ----------------
__global__ void __launch_bounds__(256) gemm_relu_kernel(const float* __restrict__ A, int lda,
                                                        const float* __restrict__ W, int ldw,
                                                        const float* __restrict__ bias,
                                                        float* __restrict__ C, int ldc, int K) {
    __shared__ float As[16][68];
    __shared__ float Ws[16][68];
    int bm = blockIdx.y * 64, bn = blockIdx.x * 64;
    int t = threadIdx.x;
    int tx = t & 15, ty = t >> 4;

    u64 acc[2][4];
#pragma unroll
    for (int i = 0; i < 2; i++)
#pragma unroll
        for (int j = 0; j < 4; j++) acc[i][j] = 0ull;

    for (int k0 = 0; k0 < K; k0 += 16) {
#pragma unroll
        for (int l = 0; l < 4; l++) {
            int e = t + l * 256;
            int m = e >> 4, kk = e & 15;
            int gk = k0 + kk;
            As[kk][m] = (gk < K) ? A[(size_t)(bm + m) * lda + gk] : 0.f;
        }
#pragma unroll
        for (int l = 0; l < 4; l++) {
            int e = t + l * 256;
            int n = e >> 4, kk = e & 15;
            int gk = k0 + kk;
            Ws[kk][n] = (gk < K) ? W[(size_t)(bn + n) * ldw + gk] : 0.f;
        }
        __syncthreads();
#pragma unroll
        for (int kk = 0; kk < 16; kk++) {
            float4 av = *(const float4*)(&As[kk][ty * 4]);
            float4 wv = *(const float4*)(&Ws[kk][tx * 4]);
            u64 ap[2] = { pk2(av.x, av.y), pk2(av.z, av.w) };
            float wvv[4] = { wv.x, wv.y, wv.z, wv.w };
#pragma unroll
            for (int j = 0; j < 4; j++) {
                u64 wd = pk2(wvv[j], wvv[j]);
                ffma2(acc[0][j], ap[0], wd);
                ffma2(acc[1][j], ap[1], wd);
            }
        }
        __syncthreads();
    }
#pragma unroll
    for (int ip = 0; ip < 2; ip++) {
#pragma unroll
        for (int j = 0; j < 4; j++) {
            float2 v = upk2(acc[ip][j]);
            int col = bn + tx * 4 + j;
            float bb = bias[col];
            int row0 = bm + ty * 4 + ip * 2;
            C[(size_t)row0 * ldc + col]       = fmaxf(v.x + bb, 0.f);
            C[(size_t)(row0 + 1) * ldc + col] = fmaxf(v.y + bb, 0.f);
        }
    }
}

// ---------------- GEMM2 + fused column-max: atomicMax into out ----------------
// Each 64-row tile lies in one batch (64 | 128). relu outputs >= 0, so
// atomicMax on int bit-patterns == float max; out must be pre-zeroed.
__global__ void __launch_bounds__(256) gemm_relu_max_kernel(const float* __restrict__ A, int lda,
                                                            const float* __restrict__ W, int ldw,
                                                            const float* __restrict__ bias,
                                                            float* __restrict__ out, int K) {
    __shared__ float As[16][68];
    __shared__ float Ws[16][68];
    __shared__ float s_cm[16][68];
    int bm = blockIdx.y * 64, bn = blockIdx.x * 64;
    int batch = bm >> 7;                       // 128 rows per batch
    int t = threadIdx.x;
    int tx = t & 15, ty = t >> 4;

    u64 acc[2][4];
#pragma unroll
    for (int i = 0; i < 2; i++)
#pragma unroll
        for (int j = 0; j < 4; j++) acc[i][j] = 0ull;

    for (int k0 = 0; k0 < K; k0 += 16) {
#pragma unroll
        for (int l = 0; l < 4; l++) {
            int e = t + l * 256;
            int m = e >> 4, kk = e & 15;
            int gk = k0 + kk;
            As[kk][m] = (gk < K) ? A[(size_t)(bm + m) * lda + gk] : 0.f;
        }
#pragma unroll
        for (int l = 0; l < 4; l++) {
            int e = t + l * 256;
            int n = e >> 4, kk = e & 15;
            int gk = k0 + kk;
            Ws[kk][n] = (gk < K) ? W[(size_t)(bn + n) * ldw + gk] : 0.f;
        }
        __syncthreads();
#pragma unroll
        for (int kk = 0; kk < 16; kk++) {
            float4 av = *(const float4*)(&As[kk][ty * 4]);
            float4 wv = *(const float4*)(&Ws[kk][tx * 4]);
            u64 ap[2] = { pk2(av.x, av.y), pk2(av.z, av.w) };
            float wvv[4] = { wv.x, wv.y, wv.z, wv.w };
#pragma unroll
            for (int j = 0; j < 4; j++) {
                u64 wd = pk2(wvv[j], wvv[j]);
                ffma2(acc[0][j], ap[0], wd);
                ffma2(acc[1][j], ap[1], wd);
            }
        }
        __syncthreads();
    }
    // per-thread max over its 4 rows per column, then block reduce
#pragma unroll
    for (int j = 0; j < 4; j++) {
        int col = tx * 4 + j;
        float bb = bias[bn + col];
        float2 v0 = upk2(acc[0][j]);
        float2 v1 = upk2(acc[1][j]);
        float m = fmaxf(fmaxf(fmaxf(v0.x + bb, 0.f), fmaxf(v0.y + bb, 0.f)),
                        fmaxf(fmaxf(v1.x + bb, 0.f), fmaxf(v1.y + bb, 0.f)));
        s_cm[ty][col] = m;
    }
    __syncthreads();
    if (t < 64) {
        float m = s_cm[0][t];
#pragma unroll
        for (int r = 1; r < 16; r++) m = fmaxf(m, s_cm[r][t]);
        atomicMax((int*)&out[batch * 1024 + bn + t], __float_as_int(m));
    }
}

// ---------------- launch ----------------
extern "C" void kernel_launch(void* const* d_in, const int* in_sizes, int n_in,
                              void* d_out, int out_size) {
    const float* x   = (const float*)d_in[0];
    const float* W1a = (const float*)d_in[1];
    const float* b1a = (const float*)d_in[2];
    const float* W1b = (const float*)d_in[3];
    const float* b1b = (const float*)d_in[4];
    const float* W2a = (const float*)d_in[5];
    const float* b2a = (const float*)d_in[6];
    const float* W2b = (const float*)d_in[7];
    const float* b2b = (const float*)d_in[8];
    const float* W3a = (const float*)d_in[9];
    const float* b3a = (const float*)d_in[10];
    const float* W3b = (const float*)d_in[11];
    const float* b3b = (const float*)d_in[12];
    float* out = (float*)d_out;

    float *xyz1, *xyz2, *feat1, *feat2, *A3, *H1;
    int *idx1, *idx2;
    cudaGetSymbolAddress((void**)&xyz1, g_xyz1);
    cudaGetSymbolAddress((void**)&xyz2, g_xyz2);
    cudaGetSymbolAddress((void**)&idx1, g_idx1);
    cudaGetSymbolAddress((void**)&idx2, g_idx2);
    cudaGetSymbolAddress((void**)&feat1, g_feat1);
    cudaGetSymbolAddress((void**)&feat2, g_feat2);
    cudaGetSymbolAddress((void**)&A3, g_A3);
    cudaGetSymbolAddress((void**)&H1, g_H1);

    static cudaStream_t sAux = nullptr;
    static cudaEvent_t evFork = nullptr, evJoin = nullptr;
    if (sAux == nullptr) {
        cudaStreamCreateWithFlags(&sAux, cudaStreamNonBlocking);
        cudaEventCreateWithFlags(&evFork, cudaEventDisableTiming);
        cudaEventCreateWithFlags(&evJoin, cudaEventDisableTiming);
    }

    const float r2_1 = (float)(0.2 * 0.2);
    const float r2_2 = (float)(0.4 * 0.4);

    // zero output (gemm2 accumulates via atomicMax)
    init_out_kernel<<<(BATCH * 1024 + 255) / 256, 256>>>(out);

    // SA1 sampling — fps1 at 256 threads (NW=8, shorter reduction path)
    size_t fps1_smem = (size_t)N1 * 3 * sizeof(float) + 2 * 8 * sizeof(u64);
    cudaFuncSetAttribute((const void*)fps_kernel<N1, 256>,
                         cudaFuncAttributeMaxDynamicSharedMemorySize, (int)fps1_smem);
    fps_kernel<N1, 256><<<BATCH, 256, fps1_smem>>>(x, xyz1, S1);

    // fork: fps2+bq2 depend only on xyz1
    cudaEventRecord(evFork, 0);
    cudaStreamWaitEvent(sAux, evFork, 0);

    ball_query_kernel<<<(BATCH * S1) / 8, 256>>>(x, xyz1, idx1, N1, S1, BATCH * S1, r2_1);
    size_t sa1_smem = (64 * 68 + 64 * 132 + 8 * 128 + 64 * 4 + 64) * sizeof(float);
    cudaFuncSetAttribute((const void*)sa1_kernel,
                         cudaFuncAttributeMaxDynamicSharedMemorySize, (int)sa1_smem);
    sa1_kernel<<<BATCH * S1, 128, sa1_smem>>>(x, xyz1, idx1, W1a, b1a, W1b, b1b, feat1);

    size_t fps2_smem = (size_t)S1 * 3 * sizeof(float) + 2 * 8 * sizeof(u64);
    fps_kernel<S1, 256><<<BATCH, 256, fps2_smem, sAux>>>(xyz1, xyz2, S2);
    ball_query_kernel<<<(BATCH * S2) / 8, 256, 0, sAux>>>(xyz1, xyz2, idx2, S1, S2, BATCH * S2, r2_2);
    cudaEventRecord(evJoin, sAux);
    cudaStreamWaitEvent(0, evJoin, 0);

    // SA2
    size_t sa2_smem = (size_t)(128 * 68 + 128 * 260 + 8 * 256) * sizeof(float);
    cudaFuncSetAttribute((const void*)sa2_kernel,
                         cudaFuncAttributeMaxDynamicSharedMemorySize, (int)sa2_smem);
    sa2_kernel<<<BATCH * S2, 256, sa2_smem>>>(xyz1, xyz2, idx2, feat1,
                                              W2a, b2a, W2b, b2b, feat2);

    // Head
    concat_kernel<<<(BATCH * S2 * 259 + 255) / 256, 256>>>(xyz2, feat2, A3);
    gemm_relu_kernel<<<dim3(512 / 64, (BATCH * S2) / 64), 256>>>(A3, 259, W3a, 259, b3a, H1, 512, 259);
    gemm_relu_max_kernel<<<dim3(1024 / 64, (BATCH * S2) / 64), 256>>>(H1, 512, W3b, 512, b3b, out, 512);
}

// round 13
// speedup vs baseline: 2.5699x; 1.1282x over previous
#include <cuda_runtime.h>
#include <cuda_bf16.h>
#include <cstdint>

#define BATCH 16
#define N1 8192
#define S1 512
#define S2 128
#define NS 64

typedef unsigned long long u64;

// ---------------- device scratch ----------------
__device__ float g_xyz1[BATCH * S1 * 3];
__device__ float g_xyz2[BATCH * S2 * 3];
__device__ int   g_idx1[BATCH * S1 * NS];
__device__ int   g_idx2[BATCH * S2 * NS];
__device__ float g_feat1[BATCH * S1 * 128];
__device__ float g_feat2[BATCH * S2 * 256];
__device__ float g_A3[BATCH * S2 * 259];
__device__ float g_H1[BATCH * S2 * 512];
__device__ float g_W2aT[131 * 128];
__device__ float g_W2bT[128 * 256];

static __device__ __forceinline__ u64 umax64(u64 a, u64 b) { return a > b ? a : b; }

// packed f32x2 helpers (bit-exact: two independent fp32 ops)
static __device__ __forceinline__ u64 pk2(float x, float y) {
    u64 r; asm("mov.b64 %0, {%1, %2};" : "=l"(r) : "f"(x), "f"(y)); return r;
}
static __device__ __forceinline__ float2 upk2(u64 v) {
    float2 f; asm("mov.b64 {%0, %1}, %2;" : "=f"(f.x), "=f"(f.y) : "l"(v)); return f;
}
static __device__ __forceinline__ void ffma2(u64& d, u64 a, u64 b) {
    asm("fma.rn.f32x2 %0, %1, %2, %0;" : "+l"(d) : "l"(a), "l"(b));
}
static __device__ __forceinline__ u64 add2(u64 a, u64 b) {
    u64 r; asm("add.rn.f32x2 %0, %1, %2;" : "=l"(r) : "l"(a), "l"(b)); return r;
}
static __device__ __forceinline__ u64 mul2(u64 a, u64 b) {
    u64 r; asm("mul.rn.f32x2 %0, %1, %2;" : "=l"(r) : "l"(a), "l"(b)); return r;
}

// ---------------- FPS ----------------
template<int N, int TPB>
__global__ void __launch_bounds__(TPB) fps_kernel(const float* __restrict__ pts,
                                                  float* __restrict__ outxyz, int NP) {
    constexpr int PPT = N / TPB;
    constexpr int PP2 = PPT / 2;
    constexpr int NW  = TPB / 32;
    extern __shared__ float sh[];
    float* s_pts = sh;                                   // N*3
    u64* s_red = (u64*)(sh + N * 3);                     // 2*NW

    int b = blockIdx.x, tid = threadIdx.x;
    int wid = tid >> 5, lane = tid & 31;
    const float* P = pts + (size_t)b * N * 3;

    u64 px2[PP2], py2[PP2], pz2[PP2];
    float mind[PPT];
#pragma unroll
    for (int p = 0; p < PP2; p++) {
        int i0 = (2 * p) * TPB + tid, i1 = (2 * p + 1) * TPB + tid;
        float x0 = P[i0 * 3 + 0], y0 = P[i0 * 3 + 1], z0 = P[i0 * 3 + 2];
        float x1 = P[i1 * 3 + 0], y1 = P[i1 * 3 + 1], z1 = P[i1 * 3 + 2];
        px2[p] = pk2(x0, x1); py2[p] = pk2(y0, y1); pz2[p] = pk2(z0, z1);
        s_pts[i0 * 3 + 0] = x0; s_pts[i0 * 3 + 1] = y0; s_pts[i0 * 3 + 2] = z0;
        s_pts[i1 * 3 + 0] = x1; s_pts[i1 * 3 + 1] = y1; s_pts[i1 * 3 + 2] = z1;
        mind[2 * p] = 1e10f; mind[2 * p + 1] = 1e10f;
    }
    __syncthreads();

    int last = 0;
    for (int it = 0; it < NP; it++) {
        if (tid == 0) {
            float* o = outxyz + ((size_t)b * NP + it) * 3;
            o[0] = s_pts[last * 3 + 0]; o[1] = s_pts[last * 3 + 1]; o[2] = s_pts[last * 3 + 2];
        }
        float lx = s_pts[last * 3 + 0], ly = s_pts[last * 3 + 1], lz = s_pts[last * 3 + 2];
        u64 nlx = pk2(-lx, -lx), nly = pk2(-ly, -ly), nlz = pk2(-lz, -lz);

        float bestm = -1.0f;
        int bestkey = 0;
#pragma unroll
        for (int p = 0; p < PP2; p++) {
            u64 dx = add2(px2[p], nlx);
            u64 dy = add2(py2[p], nly);
            u64 dz = add2(pz2[p], nlz);
            u64 ss = add2(add2(mul2(dx, dx), mul2(dy, dy)), mul2(dz, dz));
            float2 d = upk2(ss);
            float m0 = fminf(mind[2 * p], d.x);     mind[2 * p] = m0;
            float m1 = fminf(mind[2 * p + 1], d.y); mind[2 * p + 1] = m1;
            if (m0 > bestm) { bestm = m0; bestkey = N - 1 - ((2 * p) * TPB + tid); }
            if (m1 > bestm) { bestm = m1; bestkey = N - 1 - ((2 * p + 1) * TPB + tid); }
        }
        u64 best = ((u64)__float_as_uint(bestm) << 32) | (unsigned)bestkey;
#pragma unroll
        for (int off = 16; off; off >>= 1)
            best = umax64(best, __shfl_down_sync(0xffffffffu, best, off));
        if (lane == 0) s_red[(it & 1) * NW + wid] = best;
        __syncthreads();
        const u64* rr = s_red + (it & 1) * NW;
        u64 a0 = rr[0], a1 = rr[1], a2 = rr[2], a3 = rr[3];
#pragma unroll
        for (int w = 4; w < NW; w += 4) {
            a0 = umax64(a0, rr[w]); a1 = umax64(a1, rr[w + 1]);
            a2 = umax64(a2, rr[w + 2]); a3 = umax64(a3, rr[w + 3]);
        }
        last = N - 1 - (int)(umax64(umax64(a0, a1), umax64(a2, a3)) & 0xffffffffu);
    }
}

// ---------------- ball query ----------------
__global__ void ball_query_kernel(const float* __restrict__ pts,
                                  const float* __restrict__ centers,
                                  int* __restrict__ outidx,
                                  int N, int S, int total, float r2) {
    int gw = (blockIdx.x * blockDim.x + threadIdx.x) >> 5;
    int lane = threadIdx.x & 31;
    if (gw >= total) return;
    int b = gw / S;
    const float* C = centers + (size_t)gw * 3;
    float cx = C[0], cy = C[1], cz = C[2];
    float cn = __fadd_rn(__fadd_rn(__fmul_rn(cx, cx), __fmul_rn(cy, cy)), __fmul_rn(cz, cz));
    const float* P = pts + (size_t)b * N * 3;
    int* out = outidx + (size_t)gw * NS;

    int cnt = 0, firstIdx = -1;
    for (int base = 0; base < N; base += 32) {
        int i = base + lane;
        float qx = P[i * 3 + 0], qy = P[i * 3 + 1], qz = P[i * 3 + 2];
        float pn = __fadd_rn(__fadd_rn(__fmul_rn(qx, qx), __fmul_rn(qy, qy)), __fmul_rn(qz, qz));
        float dt = __fadd_rn(__fadd_rn(__fmul_rn(cx, qx), __fmul_rn(cy, qy)), __fmul_rn(cz, qz));
        float d2 = __fsub_rn(__fadd_rn(cn, pn), __fmul_rn(2.0f, dt));
        unsigned m = __ballot_sync(0xffffffffu, d2 < r2);
        if (lane == 0) {
            while (m && cnt < NS) {
                int p = __ffs(m) - 1;
                m &= m - 1;
                if (firstIdx < 0) firstIdx = base + p;
                out[cnt++] = base + p;
            }
        }
        cnt = __shfl_sync(0xffffffffu, cnt, 0);
        if (cnt >= NS) break;
    }
    if (lane == 0) {
        int fill = (cnt == 0) ? (N - 1) : firstIdx;
        for (int j = cnt; j < NS; j++) out[j] = fill;
    }
}

// ---------------- weight transposes (once per launch, off critical path) ----------------
__global__ void transpose_w2a_kernel(const float* __restrict__ W2a, float* __restrict__ W2aT) {
    int e = blockIdx.x * blockDim.x + threadIdx.x;   // 131*128
    if (e < 131 * 128) { int c = e >> 7, o = e & 127; W2aT[e] = W2a[o * 131 + c]; }
}
__global__ void transpose_w2b_kernel(const float* __restrict__ W2b, float* __restrict__ W2bT) {
    int e = blockIdx.x * blockDim.x + threadIdx.x;   // 128*256
    if (e < 128 * 256) { int c = e >> 8, o = e & 255; W2bT[e] = W2b[o * 128 + c]; }
}

// ---------------- SA1: group + MLP(3->64->128) + maxpool, FFMA2-tiled ----------------
__global__ void __launch_bounds__(128) sa1_kernel(const float* __restrict__ x,
                                                  const float* __restrict__ cxyz,
                                                  const int* __restrict__ idx,
                                                  const float* __restrict__ W1a,
                                                  const float* __restrict__ b1a,
                                                  const float* __restrict__ W1b,
                                                  const float* __restrict__ b1b,
                                                  float* __restrict__ feat) {
    extern __shared__ float s1[];
    float* s_hT   = s1;                  // [c=64][k pad 68]
    float* s_wT   = s_hT + 64 * 68;      // [c=64][o pad 132]
    float* s_m    = s_wT + 64 * 132;     // [8][128] (also W1a staging: 192 floats)
    float* s_g    = s_m + 8 * 128;       // [64][4]
    float* s_bias = s_g + 64 * 4;        // [64]

    int gblk = blockIdx.x;
    int b = gblk >> 9;
    int t = threadIdx.x;

    float cx = cxyz[gblk * 3 + 0], cy = cxyz[gblk * 3 + 1], cz = cxyz[gblk * 3 + 2];
    if (t < 64) {
        int i = idx[(size_t)gblk * NS + t];
        const float* p = x + ((size_t)b * N1 + i) * 3;
        s_g[t * 4 + 0] = p[0] - cx;
        s_g[t * 4 + 1] = p[1] - cy;
        s_g[t * 4 + 2] = p[2] - cz;
        s_bias[t] = b1a[t];
    }
    for (int e = t; e < 64 * 3; e += 128) s_m[e] = W1a[e];
    for (int e = t; e < 128 * 64; e += 128) {                       // W1b^T
        int o = e >> 6, c = e & 63;
        s_wT[c * 132 + o] = W1b[e];
    }
    __syncthreads();

    // layer1 -> s_hT[c][k]
    for (int e = t; e < 64 * 64; e += 128) {
        int k = e >> 6, o1 = e & 63;
        float v = s_g[k * 4 + 0] * s_m[o1 * 3 + 0] + s_g[k * 4 + 1] * s_m[o1 * 3 + 1]
                + s_g[k * 4 + 2] * s_m[o1 * 3 + 2] + s_bias[o1];
        s_hT[o1 * 68 + k] = fmaxf(v, 0.f);
    }
    __syncthreads();

    // layer2: C[k=64][o=128], 8k x 8o per thread, k paired for FFMA2
    int kr = t & 7, oc = t >> 3;   // oc 0..15
    u64 acc[4][8];
#pragma unroll
    for (int i = 0; i < 4; i++)
#pragma unroll
        for (int j = 0; j < 8; j++) acc[i][j] = 0ull;

    for (int c = 0; c < 64; c++) {
        const float* hr = s_hT + c * 68;
        float4 ha = *(const float4*)(hr + kr * 4);
        float4 hb = *(const float4*)(hr + 32 + kr * 4);
        u64 hp[4] = { pk2(ha.x, ha.y), pk2(ha.z, ha.w), pk2(hb.x, hb.y), pk2(hb.z, hb.w) };
        const float* wr = s_wT + c * 132;
        float4 wa = *(const float4*)(wr + oc * 4);
        float4 wb = *(const float4*)(wr + 64 + oc * 4);
        float wv[8] = { wa.x, wa.y, wa.z, wa.w, wb.x, wb.y, wb.z, wb.w };
#pragma unroll
        for (int oo = 0; oo < 8; oo++) {
            u64 wd = pk2(wv[oo], wv[oo]);
#pragma unroll
            for (int kp = 0; kp < 4; kp++) ffma2(acc[kp][oo], hp[kp], wd);
        }
    }
#pragma unroll
    for (int oo = 0; oo < 8; oo++) {
        int o = (oo < 4) ? (oc * 4 + oo) : (64 + oc * 4 + (oo - 4));
        float bias = b1b[o];
        float best = 0.f;
#pragma unroll
        for (int kp = 0; kp < 4; kp++) {
            float2 v = upk2(acc[kp][oo]);
            best = fmaxf(best, fmaxf(v.x + bias, 0.f));
            best = fmaxf(best, fmaxf(v.y + bias, 0.f));
        }
        s_m[kr * 128 + o] = best;
    }
    __syncthreads();
    if (t < 128) {
        float r = s_m[t];
#pragma unroll
        for (int w = 1; w < 8; w++) r = fmaxf(r, s_m[w * 128 + t]);
        feat[(size_t)gblk * 128 + t] = r;
    }
}

// ---------------- SA2 v2: weights read from global (L1/L2-cached), 2 blocks/SM ----------------
// Dynamic smem: h1T[128][68] + gT[131][68] + m[8][256] = 78640 B.
__global__ void __launch_bounds__(256, 2) sa2_kernel(const float* __restrict__ xyz1,
                                                     const float* __restrict__ cxyz,
                                                     const int* __restrict__ idx,
                                                     const float* __restrict__ feat1,
                                                     const float* __restrict__ W2aT,
                                                     const float* __restrict__ b2a,
                                                     const float* __restrict__ W2bT,
                                                     const float* __restrict__ b2b,
                                                     float* __restrict__ feat2) {
    extern __shared__ float s2[];
    float* s_h1T = s2;                       // [o=128][k pad 68]
    float* s_gT  = s2 + 128 * 68;            // [c=131][k pad 68]
    float* s_m   = s_gT + 131 * 68;          // [8][256]

    int gblk = blockIdx.x;
    int b = gblk >> 7;
    int t = threadIdx.x;
    float cx = cxyz[gblk * 3 + 0], cy = cxyz[gblk * 3 + 1], cz = cxyz[gblk * 3 + 2];

    // stage A: gather -> s_gT[c][k], 4 threads per k
    {
        int k = t >> 2, sub = t & 3;
        int i = idx[(size_t)gblk * NS + k];
        if (sub < 3) {
            float pv = xyz1[((size_t)b * S1 + i) * 3 + sub];
            s_gT[sub * 68 + k] = pv - (sub == 0 ? cx : (sub == 1 ? cy : cz));
        }
        const float* f = feat1 + ((size_t)b * S1 + i) * 128;
        for (int c = sub; c < 128; c += 4)
            s_gT[(3 + c) * 68 + k] = f[c];
    }
    __syncthreads();

    int kr = t & 7, oc = t >> 3;  // oc 0..31

    // stage B: h1[k=64][o=128], 8k x 4o per thread; W2aT streamed from global
    {
        u64 acc[4][4];
#pragma unroll
        for (int i = 0; i < 4; i++)
#pragma unroll
            for (int j = 0; j < 4; j++) acc[i][j] = 0ull;
        for (int c = 0; c < 131; c++) {
            const float* g = s_gT + c * 68;
            float4 ha = *(const float4*)(g + kr * 4);
            float4 hb = *(const float4*)(g + 32 + kr * 4);
            u64 hp[4] = { pk2(ha.x, ha.y), pk2(ha.z, ha.w), pk2(hb.x, hb.y), pk2(hb.z, hb.w) };
            float4 wv = __ldg((const float4*)(W2aT + c * 128 + oc * 4));
            float wvv[4] = { wv.x, wv.y, wv.z, wv.w };
#pragma unroll
            for (int oo = 0; oo < 4; oo++) {
                u64 wd = pk2(wvv[oo], wvv[oo]);
#pragma unroll
                for (int kp = 0; kp < 4; kp++) ffma2(acc[kp][oo], hp[kp], wd);
            }
        }
#pragma unroll
        for (int oo = 0; oo < 4; oo++) {
            int o = oc * 4 + oo;
            float bias = b2a[o];
#pragma unroll
            for (int kp = 0; kp < 4; kp++) {
                int k0 = (kp < 2) ? (kr * 4 + kp * 2) : (32 + kr * 4 + (kp - 2) * 2);
                float2 v = upk2(acc[kp][oo]);
                float2 r = make_float2(fmaxf(v.x + bias, 0.f), fmaxf(v.y + bias, 0.f));
                *(float2*)(s_h1T + o * 68 + k0) = r;
            }
        }
    }
    __syncthreads();

    // stage C: out[k=64][o=256], 8k x 8o per thread; W2bT streamed from global
    {
        u64 acc[4][8];
#pragma unroll
        for (int i = 0; i < 4; i++)
#pragma unroll
            for (int j = 0; j < 8; j++) acc[i][j] = 0ull;
        for (int c = 0; c < 128; c++) {
            const float* h = s_h1T + c * 68;
            float4 ha = *(const float4*)(h + kr * 4);
            float4 hb = *(const float4*)(h + 32 + kr * 4);
            u64 hp[4] = { pk2(ha.x, ha.y), pk2(ha.z, ha.w), pk2(hb.x, hb.y), pk2(hb.z, hb.w) };
            const float* w = W2bT + c * 256;
            float4 wa = __ldg((const float4*)(w + oc * 4));
            float4 wb = __ldg((const float4*)(w + 128 + oc * 4));
            float wv[8] = { wa.x, wa.y, wa.z, wa.w, wb.x, wb.y, wb.z, wb.w };
#pragma unroll
            for (int oo = 0; oo < 8; oo++) {
                u64 wd = pk2(wv[oo], wv[oo]);
#pragma unroll
                for (int kp = 0; kp < 4; kp++) ffma2(acc[kp][oo], hp[kp], wd);
            }
        }
#pragma unroll
        for (int oo = 0; oo < 8; oo++) {
            int o = (oo < 4) ? (oc * 4 + oo) : (128 + oc * 4 + (oo - 4));
            float bias = b2b[o];
            float best = 0.f;
#pragma unroll
            for (int kp = 0; kp < 4; kp++) {
                float2 v = upk2(acc[kp][oo]);
                best = fmaxf(best, fmaxf(v.x + bias, 0.f));
                best = fmaxf(best, fmaxf(v.y + bias, 0.f));
            }
            s_m[kr * 256 + o] = best;
        }
    }
    __syncthreads();
    {
        float r = s_m[t];
#pragma unroll
        for (int w = 1; w < 8; w++) r = fmaxf(r, s_m[w * 256 + t]);
        feat2[(size_t)gblk * 256 + t] = r;
    }
}

// ---------------- concat xyz2 + feat2 -> A3 [2048][259] ----------------
__global__ void concat_kernel(const float* __restrict__ xyz2,
                              const float* __restrict__ feat2,
                              float* __restrict__ A3) {
    int e = blockIdx.x * blockDim.x + threadIdx.x;
    if (e >= BATCH * S2 * 259) return;
    int r = e / 259, c = e - r * 259;
    A3[e] = (c < 3) ? xyz2[r * 3 + c] : feat2[(size_t)r * 256 + (c - 3)];
}

// ---------------- zero-init output ----------------
__global__ void init_out_kernel(float* __restrict__ out) {
    int e = blockIdx.x * blockDim.x + threadIdx.x;
    if (e < BATCH * 1024) out[e] = 0.f;
}

// ---------------- tiled GEMM: C = relu(A*W^T + bias), FFMA2 ----------------
__global__ void __launch_bounds__(256) gemm_relu_kernel(const float* __restrict__ A, int lda,
                                                        const float* __restrict__ W, int ldw,
                                                        const float* __restrict__ bias,
                                                        float* __restrict__ C, int ldc, int K) {
    __shared__ float As[16][68];
    __shared__ float Ws[16][68];
    int bm = blockIdx.y * 64, bn = blockIdx.x * 64;
    int t = threadIdx.x;
    int tx = t & 15, ty = t >> 4;

    u64 acc[2][4];
#pragma unroll
    for (int i = 0; i < 2; i++)
#pragma unroll
        for (int j = 0; j < 4; j++) acc[i][j] = 0ull;

    for (int k0 = 0; k0 < K; k0 += 16) {
#pragma unroll
        for (int l = 0; l < 4; l++) {
            int e = t + l * 256;
            int m = e >> 4, kk = e & 15;
            int gk = k0 + kk;
            As[kk][m] = (gk < K) ? A[(size_t)(bm + m) * lda + gk] : 0.f;
        }
#pragma unroll
        for (int l = 0; l < 4; l++) {
            int e = t + l * 256;
            int n = e >> 4, kk = e & 15;
            int gk = k0 + kk;
            Ws[kk][n] = (gk < K) ? W[(size_t)(bn + n) * ldw + gk] : 0.f;
        }
        __syncthreads();
#pragma unroll
        for (int kk = 0; kk < 16; kk++) {
            float4 av = *(const float4*)(&As[kk][ty * 4]);
            float4 wv = *(const float4*)(&Ws[kk][tx * 4]);
            u64 ap[2] = { pk2(av.x, av.y), pk2(av.z, av.w) };
            float wvv[4] = { wv.x, wv.y, wv.z, wv.w };
#pragma unroll
            for (int j = 0; j < 4; j++) {
                u64 wd = pk2(wvv[j], wvv[j]);
                ffma2(acc[0][j], ap[0], wd);
                ffma2(acc[1][j], ap[1], wd);
            }
        }
        __syncthreads();
    }
#pragma unroll
    for (int ip = 0; ip < 2; ip++) {
#pragma unroll
        for (int j = 0; j < 4; j++) {
            float2 v = upk2(acc[ip][j]);
            int col = bn + tx * 4 + j;
            float bb = bias[col];
            int row0 = bm + ty * 4 + ip * 2;
            C[(size_t)row0 * ldc + col]       = fmaxf(v.x + bb, 0.f);
            C[(size_t)(row0 + 1) * ldc + col] = fmaxf(v.y + bb, 0.f);
        }
    }
}

// ---------------- GEMM2 + fused column-max: atomicMax into out ----------------
__global__ void __launch_bounds__(256) gemm_relu_max_kernel(const float* __restrict__ A, int lda,
                                                            const float* __restrict__ W, int ldw,
                                                            const float* __restrict__ bias,
                                                            float* __restrict__ out, int K) {
    __shared__ float As[16][68];
    __shared__ float Ws[16][68];
    __shared__ float s_cm[16][68];
    int bm = blockIdx.y * 64, bn = blockIdx.x * 64;
    int batch = bm >> 7;                       // 128 rows per batch
    int t = threadIdx.x;
    int tx = t & 15, ty = t >> 4;

    u64 acc[2][4];
#pragma unroll
    for (int i = 0; i < 2; i++)
#pragma unroll
        for (int j = 0; j < 4; j++) acc[i][j] = 0ull;

    for (int k0 = 0; k0 < K; k0 += 16) {
#pragma unroll
        for (int l = 0; l < 4; l++) {
            int e = t + l * 256;
            int m = e >> 4, kk = e & 15;
            int gk = k0 + kk;
            As[kk][m] = (gk < K) ? A[(size_t)(bm + m) * lda + gk] : 0.f;
        }
#pragma unroll
        for (int l = 0; l < 4; l++) {
            int e = t + l * 256;
            int n = e >> 4, kk = e & 15;
            int gk = k0 + kk;
            Ws[kk][n] = (gk < K) ? W[(size_t)(bn + n) * ldw + gk] : 0.f;
        }
        __syncthreads();
#pragma unroll
        for (int kk = 0; kk < 16; kk++) {
            float4 av = *(const float4*)(&As[kk][ty * 4]);
            float4 wv = *(const float4*)(&Ws[kk][tx * 4]);
            u64 ap[2] = { pk2(av.x, av.y), pk2(av.z, av.w) };
            float wvv[4] = { wv.x, wv.y, wv.z, wv.w };
#pragma unroll
            for (int j = 0; j < 4; j++) {
                u64 wd = pk2(wvv[j], wvv[j]);
                ffma2(acc[0][j], ap[0], wd);
                ffma2(acc[1][j], ap[1], wd);
            }
        }
        __syncthreads();
    }
#pragma unroll
    for (int j = 0; j < 4; j++) {
        int col = tx * 4 + j;
        float bb = bias[bn + col];
        float2 v0 = upk2(acc[0][j]);
        float2 v1 = upk2(acc[1][j]);
        float m = fmaxf(fmaxf(fmaxf(v0.x + bb, 0.f), fmaxf(v0.y + bb, 0.f)),
                        fmaxf(fmaxf(v1.x + bb, 0.f), fmaxf(v1.y + bb, 0.f)));
        s_cm[ty][col] = m;
    }
    __syncthreads();
    if (t < 64) {
        float m = s_cm[0][t];
#pragma unroll
        for (int r = 1; r < 16; r++) m = fmaxf(m, s_cm[r][t]);
        atomicMax((int*)&out[batch * 1024 + bn + t], __float_as_int(m));
    }
}

// ---------------- launch ----------------
extern "C" void kernel_launch(void* const* d_in, const int* in_sizes, int n_in,
                              void* d_out, int out_size) {
    const float* x   = (const float*)d_in[0];
    const float* W1a = (const float*)d_in[1];
    const float* b1a = (const float*)d_in[2];
    const float* W1b = (const float*)d_in[3];
    const float* b1b = (const float*)d_in[4];
    const float* W2a = (const float*)d_in[5];
    const float* b2a = (const float*)d_in[6];
    const float* W2b = (const float*)d_in[7];
    const float* b2b = (const float*)d_in[8];
    const float* W3a = (const float*)d_in[9];
    const float* b3a = (const float*)d_in[10];
    const float* W3b = (const float*)d_in[11];
    const float* b3b = (const float*)d_in[12];
    float* out = (float*)d_out;

    float *xyz1, *xyz2, *feat1, *feat2, *A3, *H1, *W2aT, *W2bT;
    int *idx1, *idx2;
    cudaGetSymbolAddress((void**)&xyz1, g_xyz1);
    cudaGetSymbolAddress((void**)&xyz2, g_xyz2);
    cudaGetSymbolAddress((void**)&idx1, g_idx1);
    cudaGetSymbolAddress((void**)&idx2, g_idx2);
    cudaGetSymbolAddress((void**)&feat1, g_feat1);
    cudaGetSymbolAddress((void**)&feat2, g_feat2);
    cudaGetSymbolAddress((void**)&A3, g_A3);
    cudaGetSymbolAddress((void**)&H1, g_H1);
    cudaGetSymbolAddress((void**)&W2aT, g_W2aT);
    cudaGetSymbolAddress((void**)&W2bT, g_W2bT);

    static cudaStream_t sAux = nullptr;
    static cudaEvent_t evFork0 = nullptr, evFork = nullptr, evJoin = nullptr;
    if (sAux == nullptr) {
        cudaStreamCreateWithFlags(&sAux, cudaStreamNonBlocking);
        cudaEventCreateWithFlags(&evFork0, cudaEventDisableTiming);
        cudaEventCreateWithFlags(&evFork, cudaEventDisableTiming);
        cudaEventCreateWithFlags(&evJoin, cudaEventDisableTiming);
    }

    const float r2_1 = (float)(0.2 * 0.2);
    const float r2_2 = (float)(0.4 * 0.4);

    // fork immediately: init_out + weight transposes run under fps1
    cudaEventRecord(evFork0, 0);
    cudaStreamWaitEvent(sAux, evFork0, 0);
    init_out_kernel<<<(BATCH * 1024 + 255) / 256, 256, 0, sAux>>>(out);
    transpose_w2a_kernel<<<(131 * 128 + 255) / 256, 256, 0, sAux>>>(W2a, W2aT);
    transpose_w2b_kernel<<<(128 * 256 + 255) / 256, 256, 0, sAux>>>(W2b, W2bT);

    // fps1 on stream 0
    size_t fps1_smem = (size_t)N1 * 3 * sizeof(float) + 2 * 8 * sizeof(u64);
    cudaFuncSetAttribute((const void*)fps_kernel<N1, 256>,
                         cudaFuncAttributeMaxDynamicSharedMemorySize, (int)fps1_smem);
    fps_kernel<N1, 256><<<BATCH, 256, fps1_smem>>>(x, xyz1, S1);

    // fork: fps2+bq2 depend only on xyz1
    cudaEventRecord(evFork, 0);
    cudaStreamWaitEvent(sAux, evFork, 0);

    ball_query_kernel<<<(BATCH * S1) / 8, 256>>>(x, xyz1, idx1, N1, S1, BATCH * S1, r2_1);
    size_t sa1_smem = (64 * 68 + 64 * 132 + 8 * 128 + 64 * 4 + 64) * sizeof(float);
    cudaFuncSetAttribute((const void*)sa1_kernel,
                         cudaFuncAttributeMaxDynamicSharedMemorySize, (int)sa1_smem);
    sa1_kernel<<<BATCH * S1, 128, sa1_smem>>>(x, xyz1, idx1, W1a, b1a, W1b, b1b, feat1);

    size_t fps2_smem = (size_t)S1 * 3 * sizeof(float) + 2 * 8 * sizeof(u64);
    fps_kernel<S1, 256><<<BATCH, 256, fps2_smem, sAux>>>(xyz1, xyz2, S2);
    ball_query_kernel<<<(BATCH * S2) / 8, 256, 0, sAux>>>(xyz1, xyz2, idx2, S1, S2, BATCH * S2, r2_2);
    cudaEventRecord(evJoin, sAux);
    cudaStreamWaitEvent(0, evJoin, 0);

    // SA2 (2 blocks/SM: smem 78640 B)
    size_t sa2_smem = (size_t)(128 * 68 + 131 * 68 + 8 * 256) * sizeof(float);
    cudaFuncSetAttribute((const void*)sa2_kernel,
                         cudaFuncAttributeMaxDynamicSharedMemorySize, (int)sa2_smem);
    sa2_kernel<<<BATCH * S2, 256, sa2_smem>>>(xyz1, xyz2, idx2, feat1,
                                              W2aT, b2a, W2bT, b2b, feat2);

    // Head
    concat_kernel<<<(BATCH * S2 * 259 + 255) / 256, 256>>>(xyz2, feat2, A3);
    gemm_relu_kernel<<<dim3(512 / 64, (BATCH * S2) / 64), 256>>>(A3, 259, W3a, 259, b3a, H1, 512, 259);
    gemm_relu_max_kernel<<<dim3(1024 / 64, (BATCH * S2) / 64), 256>>>(H1, 512, W3b, 512, b3b, out, 512);
}